// round 2
// baseline (speedup 1.0000x reference)
#include <cuda_runtime.h>
#include <math.h>

#define B_  8
#define S_  2048
#define D_  1024
#define H_  16
#define A_  4
#define DA_ 64

// ---------------- scratch (static device memory; no allocation) ----------------
__device__ float g_xbar[B_ * D_];
__device__ float g_dist[B_ * A_];
__device__ int   g_idx [B_ * A_];
__device__ float g_Q[(size_t)B_ * A_ * S_ * DA_];   // (b*4+j, s, d)
__device__ float g_K[(size_t)B_ * A_ * S_ * DA_];
__device__ float g_V[(size_t)B_ * A_ * S_ * DA_];
__device__ float g_O[(size_t)B_ * S_ * A_ * DA_];   // (b*S+s, j*64+d)

// ---------------- kernel 0: zero xbar ----------------
__global__ void zero_xbar_kernel() {
    g_xbar[blockIdx.x * 1024 + threadIdx.x] = 0.0f;
}

// ---------------- kernel 1: xbar = mean_S x ----------------
// grid (32 s-chunks, B), block 1024 (one thread per d)
__global__ void mean_kernel(const float* __restrict__ x) {
    int b  = blockIdx.y;
    int d  = threadIdx.x;
    int s0 = blockIdx.x * 64;
    const float* xp = x + ((size_t)b * S_ + s0) * D_ + d;
    float acc = 0.0f;
    #pragma unroll 8
    for (int s = 0; s < 64; s++) acc += xp[(size_t)s * D_];
    atomicAdd(&g_xbar[b * D_ + d], acc * (1.0f / (float)S_));
}

// ---------------- kernel 2: router (r, LN, softmax, top-4) ----------------
// grid B, block 512 (warp h computes r[h])
__global__ void router_kernel(const float* __restrict__ Wr, const float* __restrict__ br,
                              const float* __restrict__ gamma, const float* __restrict__ beta) {
    int b = blockIdx.x;
    int w = threadIdx.x >> 5;      // head 0..15
    int lane = threadIdx.x & 31;
    __shared__ float r_s[H_];
    const float* xb = g_xbar + b * D_;
    float acc = 0.0f;
    for (int d = lane; d < D_; d += 32)
        acc += xb[d] * Wr[d * H_ + w];
    #pragma unroll
    for (int off = 16; off; off >>= 1) acc += __shfl_xor_sync(0xffffffffu, acc, off);
    if (lane == 0) r_s[w] = acc + br[w];
    __syncthreads();
    if (threadIdx.x == 0) {
        float r[H_];
        for (int h = 0; h < H_; h++) r[h] = r_s[h];
        float mu = 0.f;
        for (int h = 0; h < H_; h++) mu += r[h];
        mu *= (1.0f / H_);
        float var = 0.f;
        for (int h = 0; h < H_; h++) { float dd = r[h] - mu; var += dd * dd; }
        var *= (1.0f / H_);
        float inv = rsqrtf(var + 1e-5f);
        float rn[H_];
        for (int h = 0; h < H_; h++) rn[h] = (r[h] - mu) * inv * gamma[h] + beta[h];
        float mx = rn[0];
        for (int h = 1; h < H_; h++) mx = fmaxf(mx, rn[h]);
        float e[H_]; float ssum = 0.f;
        for (int h = 0; h < H_; h++) { e[h] = expf(rn[h] - mx); ssum += e[h]; }
        float isum = 1.0f / ssum;
        for (int h = 0; h < H_; h++) e[h] *= isum;
        // top-4, ties -> smaller index first (match jax top_k), then sort asc
        float tmp[H_];
        for (int h = 0; h < H_; h++) tmp[h] = e[h];
        int idx[A_];
        for (int j = 0; j < A_; j++) {
            int bi = 0; float bv = tmp[0];
            for (int h = 1; h < H_; h++) if (tmp[h] > bv) { bv = tmp[h]; bi = h; }
            idx[j] = bi; tmp[bi] = -1e30f;
        }
        for (int i = 0; i < A_; i++)
            for (int j = i + 1; j < A_; j++)
                if (idx[j] < idx[i]) { int t = idx[i]; idx[i] = idx[j]; idx[j] = t; }
        for (int j = 0; j < A_; j++) {
            g_idx [b * A_ + j] = idx[j];
            g_dist[b * A_ + j] = e[idx[j]];
        }
    }
}

// ---------------- kernel 3: gathered QKV projection ----------------
// x[b] (2048x1024) @ W_gathered (1024x256) for each of Wq,Wk,Wv
// grid (6, 16, 8): x = which*2 + ntile, y = m-tile, z = batch. block 256, 128x128x16 tile.
__global__ __launch_bounds__(256) void qkv_gemm(
    const float* __restrict__ x,
    const float* __restrict__ Wq, const float* __restrict__ bq,
    const float* __restrict__ Wk, const float* __restrict__ bk,
    const float* __restrict__ Wv, const float* __restrict__ bv)
{
    int b     = blockIdx.z;
    int mt    = blockIdx.y;
    int which = blockIdx.x >> 1;
    int n0    = (blockIdx.x & 1) * 128;

    const float* W    = which == 0 ? Wq : (which == 1 ? Wk : Wv);
    const float* bias = which == 0 ? bq : (which == 1 ? bk : bv);
    float*       Out  = which == 0 ? g_Q : (which == 1 ? g_K : g_V);

    __shared__ float As[16][132];
    __shared__ float Bs[16][128];

    int tid = threadIdx.x;
    int tx = tid & 15, ty = tid >> 4;

    int hc[2];
    hc[0] = g_idx[b * A_ + (n0 >> 6)    ] * 64;
    hc[1] = g_idx[b * A_ + (n0 >> 6) + 1] * 64;

    const float* xb = x + ((size_t)b * S_ + mt * 128) * D_;

    float acc[8][8];
    #pragma unroll
    for (int i = 0; i < 8; i++)
        #pragma unroll
        for (int j = 0; j < 8; j++) acc[i][j] = 0.f;

    for (int k0 = 0; k0 < D_; k0 += 16) {
        #pragma unroll
        for (int i = 0; i < 8; i++) {
            int e = tid + i * 256;
            int r = e >> 4, kk = e & 15;
            As[kk][r] = xb[(size_t)r * D_ + k0 + kk];
        }
        #pragma unroll
        for (int i = 0; i < 8; i++) {
            int e = tid + i * 256;
            int kk = e >> 7, nn = e & 127;
            int col = hc[nn >> 6] + (nn & 63);
            Bs[kk][nn] = W[(size_t)(k0 + kk) * (H_ * DA_) + col];
        }
        __syncthreads();
        #pragma unroll
        for (int kk = 0; kk < 16; kk++) {
            float a[8], bb[8];
            #pragma unroll
            for (int i = 0; i < 8; i++) a[i]  = As[kk][ty * 8 + i];
            #pragma unroll
            for (int j = 0; j < 8; j++) bb[j] = Bs[kk][tx * 8 + j];
            #pragma unroll
            for (int i = 0; i < 8; i++)
                #pragma unroll
                for (int j = 0; j < 8; j++) acc[i][j] += a[i] * bb[j];
        }
        __syncthreads();
    }
    #pragma unroll
    for (int i = 0; i < 8; i++) {
        int m = mt * 128 + ty * 8 + i;
        #pragma unroll
        for (int j = 0; j < 8; j++) {
            int nn = tx * 8 + j;
            int hs = nn >> 6;
            int d  = nn & 63;
            int headslot = (n0 >> 6) + hs;
            float v = acc[i][j] + bias[hc[hs] + d];
            Out[(((size_t)(b * A_ + headslot)) * S_ + m) * DA_ + d] = v;
        }
    }
}

// ---------------- kernel 4: flash attention + dist scaling ----------------
// grid (32 q-tiles of 64 rows, 32 (b,j) pairs). block 256. dynamic smem.
// smem: Qs 64 rows stride 68 | KP: K 128 rows stride 68 / P 64 rows stride 132 | Vs 128x64
#define ATTN_SMEM_FLOATS (64*68 + 128*68 + 128*64)
__global__ __launch_bounds__(256, 2) void attn_kernel() {
    extern __shared__ float sm[];
    float* Qs = sm;                    // 64*68 = 4352
    float* KP = sm + 64 * 68;          // 128*68 = 8704 (P: 64*132=8448 fits)
    float* Vs = KP + 128 * 68;         // 128*64 = 8192

    int qt = blockIdx.x;
    int bj = blockIdx.y;
    int b  = bj >> 2, js = bj & 3;
    int tid = threadIdx.x;
    int rg = tid >> 4;                 // row group: rows rg*4 .. rg*4+3
    int cg = tid & 15;                 // col group

    const float* Qg = g_Q + (size_t)bj * S_ * DA_ + (size_t)qt * 64 * DA_;
    const float* Kg = g_K + (size_t)bj * S_ * DA_;
    const float* Vg = g_V + (size_t)bj * S_ * DA_;

    #pragma unroll
    for (int i = 0; i < 16; i++) {
        int e = tid + i * 256;
        int r = e >> 6, d = e & 63;
        Qs[r * 68 + d] = Qg[e];
    }

    float m_i[4], l_i[4], o[4][4];
    #pragma unroll
    for (int i = 0; i < 4; i++) {
        m_i[i] = -1e30f; l_i[i] = 0.f;
        #pragma unroll
        for (int j = 0; j < 4; j++) o[i][j] = 0.f;
    }

    for (int t = 0; t < 16; t++) {
        __syncthreads();  // protect KP/Vs from previous iteration readers
        const float* Kt = Kg + (size_t)t * 128 * DA_;
        const float* Vt = Vg + (size_t)t * 128 * DA_;
        #pragma unroll
        for (int i = 0; i < 32; i++) {
            int e = tid + i * 256;
            int r = e >> 6, d = e & 63;
            KP[r * 68 + d] = Kt[e];
            Vs[e] = Vt[e];
        }
        __syncthreads();

        // scores: rows rg*4+i, cols cg + 16*j
        float s[4][8];
        #pragma unroll
        for (int i = 0; i < 4; i++)
            #pragma unroll
            for (int j = 0; j < 8; j++) s[i][j] = 0.f;

        #pragma unroll
        for (int d0 = 0; d0 < 64; d0 += 4) {
            float4 q[4], k[8];
            #pragma unroll
            for (int i = 0; i < 4; i++) q[i] = *(const float4*)&Qs[(rg * 4 + i) * 68 + d0];
            #pragma unroll
            for (int j = 0; j < 8; j++) k[j] = *(const float4*)&KP[(cg + 16 * j) * 68 + d0];
            #pragma unroll
            for (int i = 0; i < 4; i++)
                #pragma unroll
                for (int j = 0; j < 8; j++)
                    s[i][j] += q[i].x * k[j].x + q[i].y * k[j].y
                             + q[i].z * k[j].z + q[i].w * k[j].w;
        }
        #pragma unroll
        for (int i = 0; i < 4; i++)
            #pragma unroll
            for (int j = 0; j < 8; j++) s[i][j] *= 0.125f;

        // online softmax (per row, reduced across the 16 cg threads via shfl)
        float corr[4];
        #pragma unroll
        for (int i = 0; i < 4; i++) {
            float mx = s[i][0];
            #pragma unroll
            for (int j = 1; j < 8; j++) mx = fmaxf(mx, s[i][j]);
            #pragma unroll
            for (int off = 8; off; off >>= 1) mx = fmaxf(mx, __shfl_xor_sync(0xffffffffu, mx, off));
            float mnew = fmaxf(m_i[i], mx);
            corr[i] = __expf(m_i[i] - mnew);
            float ts = 0.f;
            #pragma unroll
            for (int j = 0; j < 8; j++) { float p = __expf(s[i][j] - mnew); s[i][j] = p; ts += p; }
            #pragma unroll
            for (int off = 8; off; off >>= 1) ts += __shfl_xor_sync(0xffffffffu, ts, off);
            l_i[i] = l_i[i] * corr[i] + ts;
            m_i[i] = mnew;
            #pragma unroll
            for (int j = 0; j < 4; j++) o[i][j] *= corr[i];
        }
        __syncthreads();  // all warps done reading K from KP

        // store P into KP (64 rows, stride 132)
        #pragma unroll
        for (int i = 0; i < 4; i++)
            #pragma unroll
            for (int j = 0; j < 8; j++)
                KP[(rg * 4 + i) * 132 + cg + 16 * j] = s[i][j];
        __syncthreads();

        // PV: each thread accumulates rows rg*4+i, dims cg*4 + jd
        #pragma unroll 4
        for (int k2 = 0; k2 < 128; k2++) {
            float4 v = *(const float4*)&Vs[k2 * 64 + cg * 4];
            float pr[4];
            #pragma unroll
            for (int i = 0; i < 4; i++) pr[i] = KP[(rg * 4 + i) * 132 + k2];
            #pragma unroll
            for (int i = 0; i < 4; i++) {
                o[i][0] += pr[i] * v.x;
                o[i][1] += pr[i] * v.y;
                o[i][2] += pr[i] * v.z;
                o[i][3] += pr[i] * v.w;
            }
        }
    }

    float dist = g_dist[b * A_ + js];
    #pragma unroll
    for (int i = 0; i < 4; i++) {
        int srow = qt * 64 + rg * 4 + i;
        float inv = dist / l_i[i];
        float* zp = g_O + ((size_t)(b * S_ + srow)) * (A_ * DA_) + js * 64 + cg * 4;
        zp[0] = o[i][0] * inv;
        zp[1] = o[i][1] * inv;
        zp[2] = o[i][2] * inv;
        zp[3] = o[i][3] * inv;
    }
}

// ---------------- kernel 5: Z = O_final @ Wo + bo ----------------
// M=16384, N=1024, K=256. grid (8, 128), block 256, 128x128x16 tile.
__global__ __launch_bounds__(256) void out_gemm(
    const float* __restrict__ Wo, const float* __restrict__ bo,
    float* __restrict__ Z)
{
    int m0 = blockIdx.y * 128;
    int n0 = blockIdx.x * 128;
    __shared__ float As[16][132];
    __shared__ float Bs[16][128];
    int tid = threadIdx.x;
    int tx = tid & 15, ty = tid >> 4;

    float acc[8][8];
    #pragma unroll
    for (int i = 0; i < 8; i++)
        #pragma unroll
        for (int j = 0; j < 8; j++) acc[i][j] = 0.f;

    for (int k0 = 0; k0 < A_ * DA_; k0 += 16) {
        #pragma unroll
        for (int i = 0; i < 8; i++) {
            int e = tid + i * 256;
            int r = e >> 4, kk = e & 15;
            As[kk][r] = g_O[(size_t)(m0 + r) * (A_ * DA_) + k0 + kk];
        }
        #pragma unroll
        for (int i = 0; i < 8; i++) {
            int e = tid + i * 256;
            int kk = e >> 7, nn = e & 127;
            Bs[kk][nn] = Wo[(size_t)(k0 + kk) * D_ + n0 + nn];
        }
        __syncthreads();
        #pragma unroll
        for (int kk = 0; kk < 16; kk++) {
            float a[8], bb[8];
            #pragma unroll
            for (int i = 0; i < 8; i++) a[i]  = As[kk][ty * 8 + i];
            #pragma unroll
            for (int j = 0; j < 8; j++) bb[j] = Bs[kk][tx * 8 + j];
            #pragma unroll
            for (int i = 0; i < 8; i++)
                #pragma unroll
                for (int j = 0; j < 8; j++) acc[i][j] += a[i] * bb[j];
        }
        __syncthreads();
    }
    #pragma unroll
    for (int i = 0; i < 8; i++) {
        int m = m0 + ty * 8 + i;
        #pragma unroll
        for (int j = 0; j < 8; j++) {
            int n = n0 + tx * 8 + j;
            Z[(size_t)m * D_ + n] = acc[i][j] + bo[n];
        }
    }
}

// ---------------- launch ----------------
extern "C" void kernel_launch(void* const* d_in, const int* in_sizes, int n_in,
                              void* d_out, int out_size) {
    const float* x     = (const float*)d_in[0];
    const float* Wq    = (const float*)d_in[1];
    const float* bq    = (const float*)d_in[2];
    const float* Wk    = (const float*)d_in[3];
    const float* bk    = (const float*)d_in[4];
    const float* Wv    = (const float*)d_in[5];
    const float* bv    = (const float*)d_in[6];
    const float* Wr    = (const float*)d_in[7];
    const float* br    = (const float*)d_in[8];
    const float* gamma = (const float*)d_in[9];
    const float* beta  = (const float*)d_in[10];
    const float* Wo    = (const float*)d_in[11];
    const float* bo    = (const float*)d_in[12];
    float* Z = (float*)d_out;

    cudaFuncSetAttribute(attn_kernel, cudaFuncAttributeMaxDynamicSharedMemorySize,
                         ATTN_SMEM_FLOATS * (int)sizeof(float));

    zero_xbar_kernel<<<B_, 1024>>>();
    mean_kernel<<<dim3(32, B_), 1024>>>(x);
    router_kernel<<<B_, 512>>>(Wr, br, gamma, beta);
    qkv_gemm<<<dim3(6, 16, B_), 256>>>(x, Wq, bq, Wk, bk, Wv, bv);
    attn_kernel<<<dim3(32, 32), 256, ATTN_SMEM_FLOATS * (int)sizeof(float)>>>();
    out_gemm<<<dim3(8, 128), 256>>>(Wo, bo, Z);
}

// round 4
// speedup vs baseline: 1.4253x; 1.4253x over previous
#include <cuda_runtime.h>
#include <math.h>
#include <stdint.h>

#define B_  8
#define S_  2048
#define D_  1024
#define H_  16
#define A_  4
#define DA_ 64

// ---------------- scratch (static device memory; no allocation) ----------------
__device__ float g_xbar[B_ * D_];
__device__ float g_dist[B_ * A_];
__device__ int   g_idx [B_ * A_];
__device__ float g_Q[(size_t)B_ * A_ * S_ * DA_];   // (b*4+j, s, d)
__device__ float g_K[(size_t)B_ * A_ * S_ * DA_];
__device__ float g_V[(size_t)B_ * A_ * S_ * DA_];
__device__ float g_O[(size_t)B_ * S_ * A_ * DA_];   // (b*S+s, j*64+d)

// ---------------- helpers ----------------
__device__ __forceinline__ float f2tf32(float x) {
    asm("cvt.rna.tf32.f32 %0, %0;" : "+f"(x));
    return x;
}

__device__ __forceinline__ void mma_tf32(float* c,
    uint32_t a0, uint32_t a1, uint32_t a2, uint32_t a3,
    uint32_t b0, uint32_t b1)
{
    asm volatile(
        "mma.sync.aligned.m16n8k8.row.col.f32.tf32.tf32.f32 "
        "{%0,%1,%2,%3}, {%4,%5,%6,%7}, {%8,%9}, {%0,%1,%2,%3};"
        : "+f"(c[0]), "+f"(c[1]), "+f"(c[2]), "+f"(c[3])
        : "r"(a0), "r"(a1), "r"(a2), "r"(a3), "r"(b0), "r"(b1));
}

// ---------------- kernel 0: zero xbar ----------------
__global__ void zero_xbar_kernel() {
    g_xbar[blockIdx.x * 1024 + threadIdx.x] = 0.0f;
}

// ---------------- kernel 1: xbar = mean_S x ----------------
__global__ void mean_kernel(const float* __restrict__ x) {
    int b  = blockIdx.y;
    int d  = threadIdx.x;
    int s0 = blockIdx.x * 64;
    const float* xp = x + ((size_t)b * S_ + s0) * D_ + d;
    float acc = 0.0f;
    #pragma unroll 8
    for (int s = 0; s < 64; s++) acc += xp[(size_t)s * D_];
    atomicAdd(&g_xbar[b * D_ + d], acc * (1.0f / (float)S_));
}

// ---------------- kernel 2: router ----------------
__global__ void router_kernel(const float* __restrict__ Wr, const float* __restrict__ br,
                              const float* __restrict__ gamma, const float* __restrict__ beta) {
    int b = blockIdx.x;
    int w = threadIdx.x >> 5;
    int lane = threadIdx.x & 31;
    __shared__ float r_s[H_];
    const float* xb = g_xbar + b * D_;
    float acc = 0.0f;
    for (int d = lane; d < D_; d += 32)
        acc += xb[d] * Wr[d * H_ + w];
    #pragma unroll
    for (int off = 16; off; off >>= 1) acc += __shfl_xor_sync(0xffffffffu, acc, off);
    if (lane == 0) r_s[w] = acc + br[w];
    __syncthreads();
    if (threadIdx.x == 0) {
        float r[H_];
        for (int h = 0; h < H_; h++) r[h] = r_s[h];
        float mu = 0.f;
        for (int h = 0; h < H_; h++) mu += r[h];
        mu *= (1.0f / H_);
        float var = 0.f;
        for (int h = 0; h < H_; h++) { float dd = r[h] - mu; var += dd * dd; }
        var *= (1.0f / H_);
        float inv = rsqrtf(var + 1e-5f);
        float rn[H_];
        for (int h = 0; h < H_; h++) rn[h] = (r[h] - mu) * inv * gamma[h] + beta[h];
        float mx = rn[0];
        for (int h = 1; h < H_; h++) mx = fmaxf(mx, rn[h]);
        float e[H_]; float ssum = 0.f;
        for (int h = 0; h < H_; h++) { e[h] = expf(rn[h] - mx); ssum += e[h]; }
        float isum = 1.0f / ssum;
        for (int h = 0; h < H_; h++) e[h] *= isum;
        float tmp[H_];
        for (int h = 0; h < H_; h++) tmp[h] = e[h];
        int idx[A_];
        for (int j = 0; j < A_; j++) {
            int bi = 0; float bv = tmp[0];
            for (int h = 1; h < H_; h++) if (tmp[h] > bv) { bv = tmp[h]; bi = h; }
            idx[j] = bi; tmp[bi] = -1e30f;
        }
        for (int i = 0; i < A_; i++)
            for (int j = i + 1; j < A_; j++)
                if (idx[j] < idx[i]) { int t = idx[i]; idx[i] = idx[j]; idx[j] = t; }
        for (int j = 0; j < A_; j++) {
            g_idx [b * A_ + j] = idx[j];
            g_dist[b * A_ + j] = e[idx[j]];
        }
    }
}

// ---------------- kernel 3: gathered QKV projection (tf32 tensor cores) ----------------
// per (b, which, ntile): x[b] (2048x1024) @ Wg (1024x128)
// grid (6, 16, 8). block 256 = 8 warps, tile 128x128x16, warp tile 64x32.
__global__ __launch_bounds__(256) void qkv_gemm_tf32(
    const float* __restrict__ x,
    const float* __restrict__ Wq, const float* __restrict__ bq,
    const float* __restrict__ Wk, const float* __restrict__ bk,
    const float* __restrict__ Wv, const float* __restrict__ bv)
{
    int b     = blockIdx.z;
    int mt    = blockIdx.y;
    int which = blockIdx.x >> 1;
    int n0    = (blockIdx.x & 1) * 128;

    const float* W    = which == 0 ? Wq : (which == 1 ? Wk : Wv);
    const float* bias = which == 0 ? bq : (which == 1 ? bk : bv);
    float*       Out  = which == 0 ? g_Q : (which == 1 ? g_K : g_V);

    __shared__ float As[2][128][20];   // [buf][m][k], stride 20 -> conflict-free frags
    __shared__ float Bs[2][16][136];   // [buf][k][n], stride 136 -> conflict-free frags

    int tid  = threadIdx.x;
    int wid  = tid >> 5;
    int lane = tid & 31;
    int g    = lane >> 2, q = lane & 3;
    int wm   = (wid >> 2) * 64;        // warp m offset (0/64)
    int wn   = (wid & 3) * 32;         // warp n offset

    int hc[2];
    hc[0] = g_idx[b * A_ + (n0 >> 6)    ] * 64;
    hc[1] = g_idx[b * A_ + (n0 >> 6) + 1] * 64;

    const float* xb = x + ((size_t)b * S_ + (size_t)mt * 128) * D_;

    float acc[4][4][4];
    #pragma unroll
    for (int mi = 0; mi < 4; mi++)
        #pragma unroll
        for (int ni = 0; ni < 4; ni++)
            #pragma unroll
            for (int c = 0; c < 4; c++) acc[mi][ni][c] = 0.f;

    float4 ra[2], rb[2];

    // ---- stage k0 into regs ----
    auto ldg_tile = [&](int k0) {
        #pragma unroll
        for (int i = 0; i < 2; i++) {
            int f   = tid + i * 256;
            int row = f >> 2, kc = (f & 3) * 4;
            ra[i] = *(const float4*)(xb + (size_t)row * D_ + k0 + kc);
        }
        #pragma unroll
        for (int i = 0; i < 2; i++) {
            int f   = tid + i * 256;
            int kk  = f >> 5, nn = (f & 31) * 4;
            int col = hc[nn >> 6] + (nn & 63);
            rb[i] = *(const float4*)(W + (size_t)(k0 + kk) * (H_ * DA_) + col);
        }
    };
    auto sts_tile = [&](int buf) {
        #pragma unroll
        for (int i = 0; i < 2; i++) {
            int f   = tid + i * 256;
            int row = f >> 2, kc = (f & 3) * 4;
            As[buf][row][kc + 0] = f2tf32(ra[i].x);
            As[buf][row][kc + 1] = f2tf32(ra[i].y);
            As[buf][row][kc + 2] = f2tf32(ra[i].z);
            As[buf][row][kc + 3] = f2tf32(ra[i].w);
        }
        #pragma unroll
        for (int i = 0; i < 2; i++) {
            int f  = tid + i * 256;
            int kk = f >> 5, nn = (f & 31) * 4;
            Bs[buf][kk][nn + 0] = f2tf32(rb[i].x);
            Bs[buf][kk][nn + 1] = f2tf32(rb[i].y);
            Bs[buf][kk][nn + 2] = f2tf32(rb[i].z);
            Bs[buf][kk][nn + 3] = f2tf32(rb[i].w);
        }
    };
    auto compute = [&](int buf) {
        #pragma unroll
        for (int kk = 0; kk < 16; kk += 8) {
            uint32_t afr[4][4], bfr[4][2];
            #pragma unroll
            for (int mi = 0; mi < 4; mi++) {
                int m = wm + mi * 16 + g;
                afr[mi][0] = __float_as_uint(As[buf][m    ][kk + q    ]);
                afr[mi][1] = __float_as_uint(As[buf][m + 8][kk + q    ]);
                afr[mi][2] = __float_as_uint(As[buf][m    ][kk + q + 4]);
                afr[mi][3] = __float_as_uint(As[buf][m + 8][kk + q + 4]);
            }
            #pragma unroll
            for (int ni = 0; ni < 4; ni++) {
                int n = wn + ni * 8 + g;
                bfr[ni][0] = __float_as_uint(Bs[buf][kk + q    ][n]);
                bfr[ni][1] = __float_as_uint(Bs[buf][kk + q + 4][n]);
            }
            #pragma unroll
            for (int mi = 0; mi < 4; mi++)
                #pragma unroll
                for (int ni = 0; ni < 4; ni++)
                    mma_tf32(acc[mi][ni], afr[mi][0], afr[mi][1], afr[mi][2], afr[mi][3],
                             bfr[ni][0], bfr[ni][1]);
        }
    };

    ldg_tile(0);
    sts_tile(0);
    __syncthreads();
    int buf = 0;
    for (int k0 = 16; k0 <= D_; k0 += 16) {
        bool has = (k0 < D_);
        if (has) ldg_tile(k0);
        compute(buf);
        if (has) sts_tile(buf ^ 1);
        __syncthreads();
        buf ^= 1;
    }

    // epilogue
    #pragma unroll
    for (int mi = 0; mi < 4; mi++) {
        int m = mt * 128 + wm + mi * 16 + g;
        #pragma unroll
        for (int ni = 0; ni < 4; ni++) {
            int nn = wn + ni * 8 + q * 2;
            int hs = nn >> 6, d = nn & 63;
            int headslot = (n0 >> 6) + hs;
            float bz0 = bias[hc[hs] + d];
            float bz1 = bias[hc[hs] + d + 1];
            float* outp = Out + (((size_t)(b * A_ + headslot)) * S_) * DA_ + d;
            outp[(size_t)m * DA_ + 0]       = acc[mi][ni][0] + bz0;
            outp[(size_t)m * DA_ + 1]       = acc[mi][ni][1] + bz1;
            outp[(size_t)(m + 8) * DA_ + 0] = acc[mi][ni][2] + bz0;
            outp[(size_t)(m + 8) * DA_ + 1] = acc[mi][ni][3] + bz1;
        }
    }
}

// ---------------- kernel 4: flash attention + dist scaling (fp32, unchanged) ----------------
#define ATTN_SMEM_FLOATS (64*68 + 128*68 + 128*64)
__global__ __launch_bounds__(256, 2) void attn_kernel() {
    extern __shared__ float sm[];
    float* Qs = sm;
    float* KP = sm + 64 * 68;
    float* Vs = KP + 128 * 68;

    int qt = blockIdx.x;
    int bj = blockIdx.y;
    int b  = bj >> 2, js = bj & 3;
    int tid = threadIdx.x;
    int rg = tid >> 4;
    int cg = tid & 15;

    const float* Qg = g_Q + (size_t)bj * S_ * DA_ + (size_t)qt * 64 * DA_;
    const float* Kg = g_K + (size_t)bj * S_ * DA_;
    const float* Vg = g_V + (size_t)bj * S_ * DA_;

    #pragma unroll
    for (int i = 0; i < 16; i++) {
        int e = tid + i * 256;
        int r = e >> 6, d = e & 63;
        Qs[r * 68 + d] = Qg[e];
    }

    float m_i[4], l_i[4], o[4][4];
    #pragma unroll
    for (int i = 0; i < 4; i++) {
        m_i[i] = -1e30f; l_i[i] = 0.f;
        #pragma unroll
        for (int j = 0; j < 4; j++) o[i][j] = 0.f;
    }

    for (int t = 0; t < 16; t++) {
        __syncthreads();
        const float* Kt = Kg + (size_t)t * 128 * DA_;
        const float* Vt = Vg + (size_t)t * 128 * DA_;
        #pragma unroll
        for (int i = 0; i < 32; i++) {
            int e = tid + i * 256;
            int r = e >> 6, d = e & 63;
            KP[r * 68 + d] = Kt[e];
            Vs[e] = Vt[e];
        }
        __syncthreads();

        float s[4][8];
        #pragma unroll
        for (int i = 0; i < 4; i++)
            #pragma unroll
            for (int j = 0; j < 8; j++) s[i][j] = 0.f;

        #pragma unroll
        for (int d0 = 0; d0 < 64; d0 += 4) {
            float4 qv[4], kv[8];
            #pragma unroll
            for (int i = 0; i < 4; i++) qv[i] = *(const float4*)&Qs[(rg * 4 + i) * 68 + d0];
            #pragma unroll
            for (int j = 0; j < 8; j++) kv[j] = *(const float4*)&KP[(cg + 16 * j) * 68 + d0];
            #pragma unroll
            for (int i = 0; i < 4; i++)
                #pragma unroll
                for (int j = 0; j < 8; j++)
                    s[i][j] += qv[i].x * kv[j].x + qv[i].y * kv[j].y
                             + qv[i].z * kv[j].z + qv[i].w * kv[j].w;
        }
        #pragma unroll
        for (int i = 0; i < 4; i++)
            #pragma unroll
            for (int j = 0; j < 8; j++) s[i][j] *= 0.125f;

        float corr[4];
        #pragma unroll
        for (int i = 0; i < 4; i++) {
            float mx = s[i][0];
            #pragma unroll
            for (int j = 1; j < 8; j++) mx = fmaxf(mx, s[i][j]);
            #pragma unroll
            for (int off = 8; off; off >>= 1) mx = fmaxf(mx, __shfl_xor_sync(0xffffffffu, mx, off));
            float mnew = fmaxf(m_i[i], mx);
            corr[i] = __expf(m_i[i] - mnew);
            float ts = 0.f;
            #pragma unroll
            for (int j = 0; j < 8; j++) { float p = __expf(s[i][j] - mnew); s[i][j] = p; ts += p; }
            #pragma unroll
            for (int off = 8; off; off >>= 1) ts += __shfl_xor_sync(0xffffffffu, ts, off);
            l_i[i] = l_i[i] * corr[i] + ts;
            m_i[i] = mnew;
            #pragma unroll
            for (int j = 0; j < 4; j++) o[i][j] *= corr[i];
        }
        __syncthreads();

        #pragma unroll
        for (int i = 0; i < 4; i++)
            #pragma unroll
            for (int j = 0; j < 8; j++)
                KP[(rg * 4 + i) * 132 + cg + 16 * j] = s[i][j];
        __syncthreads();

        #pragma unroll 4
        for (int k2 = 0; k2 < 128; k2++) {
            float4 v = *(const float4*)&Vs[k2 * 64 + cg * 4];
            float pr[4];
            #pragma unroll
            for (int i = 0; i < 4; i++) pr[i] = KP[(rg * 4 + i) * 132 + k2];
            #pragma unroll
            for (int i = 0; i < 4; i++) {
                o[i][0] += pr[i] * v.x;
                o[i][1] += pr[i] * v.y;
                o[i][2] += pr[i] * v.z;
                o[i][3] += pr[i] * v.w;
            }
        }
    }

    float dist = g_dist[b * A_ + js];
    #pragma unroll
    for (int i = 0; i < 4; i++) {
        int srow = qt * 64 + rg * 4 + i;
        float inv = dist / l_i[i];
        float* zp = g_O + ((size_t)(b * S_ + srow)) * (A_ * DA_) + js * 64 + cg * 4;
        zp[0] = o[i][0] * inv;
        zp[1] = o[i][1] * inv;
        zp[2] = o[i][2] * inv;
        zp[3] = o[i][3] * inv;
    }
}

// ---------------- kernel 5: Z = O_final @ Wo + bo (tf32 tensor cores) ----------------
// M=16384, N=1024, K=256. grid (8 ntiles, 128 mtiles), block 256, tile 128x128x16.
__global__ __launch_bounds__(256) void out_gemm_tf32(
    const float* __restrict__ Wo, const float* __restrict__ bo,
    float* __restrict__ Z)
{
    int m0 = blockIdx.y * 128;
    int n0 = blockIdx.x * 128;

    __shared__ float As[2][128][20];
    __shared__ float Bs[2][16][136];

    int tid  = threadIdx.x;
    int wid  = tid >> 5;
    int lane = tid & 31;
    int g    = lane >> 2, q = lane & 3;
    int wm   = (wid >> 2) * 64;
    int wn   = (wid & 3) * 32;

    float acc[4][4][4];
    #pragma unroll
    for (int mi = 0; mi < 4; mi++)
        #pragma unroll
        for (int ni = 0; ni < 4; ni++)
            #pragma unroll
            for (int c = 0; c < 4; c++) acc[mi][ni][c] = 0.f;

    float4 ra[2], rb[2];

    auto ldg_tile = [&](int k0) {
        #pragma unroll
        for (int i = 0; i < 2; i++) {
            int f   = tid + i * 256;
            int row = f >> 2, kc = (f & 3) * 4;
            ra[i] = *(const float4*)(g_O + (size_t)(m0 + row) * (A_ * DA_) + k0 + kc);
        }
        #pragma unroll
        for (int i = 0; i < 2; i++) {
            int f  = tid + i * 256;
            int kk = f >> 5, nn = (f & 31) * 4;
            rb[i] = *(const float4*)(Wo + (size_t)(k0 + kk) * D_ + n0 + nn);
        }
    };
    auto sts_tile = [&](int buf) {
        #pragma unroll
        for (int i = 0; i < 2; i++) {
            int f   = tid + i * 256;
            int row = f >> 2, kc = (f & 3) * 4;
            As[buf][row][kc + 0] = f2tf32(ra[i].x);
            As[buf][row][kc + 1] = f2tf32(ra[i].y);
            As[buf][row][kc + 2] = f2tf32(ra[i].z);
            As[buf][row][kc + 3] = f2tf32(ra[i].w);
        }
        #pragma unroll
        for (int i = 0; i < 2; i++) {
            int f  = tid + i * 256;
            int kk = f >> 5, nn = (f & 31) * 4;
            Bs[buf][kk][nn + 0] = f2tf32(rb[i].x);
            Bs[buf][kk][nn + 1] = f2tf32(rb[i].y);
            Bs[buf][kk][nn + 2] = f2tf32(rb[i].z);
            Bs[buf][kk][nn + 3] = f2tf32(rb[i].w);
        }
    };
    auto compute = [&](int buf) {
        #pragma unroll
        for (int kk = 0; kk < 16; kk += 8) {
            uint32_t afr[4][4], bfr[4][2];
            #pragma unroll
            for (int mi = 0; mi < 4; mi++) {
                int m = wm + mi * 16 + g;
                afr[mi][0] = __float_as_uint(As[buf][m    ][kk + q    ]);
                afr[mi][1] = __float_as_uint(As[buf][m + 8][kk + q    ]);
                afr[mi][2] = __float_as_uint(As[buf][m    ][kk + q + 4]);
                afr[mi][3] = __float_as_uint(As[buf][m + 8][kk + q + 4]);
            }
            #pragma unroll
            for (int ni = 0; ni < 4; ni++) {
                int n = wn + ni * 8 + g;
                bfr[ni][0] = __float_as_uint(Bs[buf][kk + q    ][n]);
                bfr[ni][1] = __float_as_uint(Bs[buf][kk + q + 4][n]);
            }
            #pragma unroll
            for (int mi = 0; mi < 4; mi++)
                #pragma unroll
                for (int ni = 0; ni < 4; ni++)
                    mma_tf32(acc[mi][ni], afr[mi][0], afr[mi][1], afr[mi][2], afr[mi][3],
                             bfr[ni][0], bfr[ni][1]);
        }
    };

    ldg_tile(0);
    sts_tile(0);
    __syncthreads();
    int buf = 0;
    for (int k0 = 16; k0 <= A_ * DA_; k0 += 16) {
        bool has = (k0 < A_ * DA_);
        if (has) ldg_tile(k0);
        compute(buf);
        if (has) sts_tile(buf ^ 1);
        __syncthreads();
        buf ^= 1;
    }

    #pragma unroll
    for (int mi = 0; mi < 4; mi++) {
        int m = m0 + wm + mi * 16 + g;
        #pragma unroll
        for (int ni = 0; ni < 4; ni++) {
            int n = n0 + wn + ni * 8 + q * 2;
            float b0v = bo[n], b1v = bo[n + 1];
            Z[(size_t)m * D_ + n]           = acc[mi][ni][0] + b0v;
            Z[(size_t)m * D_ + n + 1]       = acc[mi][ni][1] + b1v;
            Z[(size_t)(m + 8) * D_ + n]     = acc[mi][ni][2] + b0v;
            Z[(size_t)(m + 8) * D_ + n + 1] = acc[mi][ni][3] + b1v;
        }
    }
}

// ---------------- launch ----------------
extern "C" void kernel_launch(void* const* d_in, const int* in_sizes, int n_in,
                              void* d_out, int out_size) {
    const float* x     = (const float*)d_in[0];
    const float* Wq    = (const float*)d_in[1];
    const float* bq    = (const float*)d_in[2];
    const float* Wk    = (const float*)d_in[3];
    const float* bk    = (const float*)d_in[4];
    const float* Wv    = (const float*)d_in[5];
    const float* bv    = (const float*)d_in[6];
    const float* Wr    = (const float*)d_in[7];
    const float* br    = (const float*)d_in[8];
    const float* gamma = (const float*)d_in[9];
    const float* beta  = (const float*)d_in[10];
    const float* Wo    = (const float*)d_in[11];
    const float* bo    = (const float*)d_in[12];
    float* Z = (float*)d_out;

    cudaFuncSetAttribute(attn_kernel, cudaFuncAttributeMaxDynamicSharedMemorySize,
                         ATTN_SMEM_FLOATS * (int)sizeof(float));

    zero_xbar_kernel<<<B_, 1024>>>();
    mean_kernel<<<dim3(32, B_), 1024>>>(x);
    router_kernel<<<B_, 512>>>(Wr, br, gamma, beta);
    qkv_gemm_tf32<<<dim3(6, 16, B_), 256>>>(x, Wq, bq, Wk, bk, Wv, bv);
    attn_kernel<<<dim3(32, 32), 256, ATTN_SMEM_FLOATS * (int)sizeof(float)>>>();
    out_gemm_tf32<<<dim3(8, 128), 256>>>(Wo, bo, Z);
}

// round 8
// speedup vs baseline: 1.6662x; 1.1690x over previous
#include <cuda_runtime.h>
#include <math.h>
#include <stdint.h>

#define B_  8
#define S_  2048
#define D_  1024
#define H_  16
#define A_  4
#define DA_ 64

// ---------------- scratch (static device memory; no allocation) ----------------
__device__ float g_xbar[B_ * D_];
__device__ float g_dist[B_ * A_];
__device__ int   g_idx [B_ * A_];
__device__ float g_Q[(size_t)B_ * A_ * S_ * DA_];   // (b*4+j, s, d)
__device__ float g_K[(size_t)B_ * A_ * S_ * DA_];
__device__ float g_V[(size_t)B_ * A_ * S_ * DA_];
__device__ float g_O[(size_t)B_ * S_ * A_ * DA_];   // (b*S+s, j*64+d)

// ---------------- helpers ----------------
__device__ __forceinline__ float f2tf32(float x) {
    asm("cvt.rna.tf32.f32 %0, %0;" : "+f"(x));
    return x;
}

__device__ __forceinline__ void mma_tf32(float* c,
    uint32_t a0, uint32_t a1, uint32_t a2, uint32_t a3,
    uint32_t b0, uint32_t b1)
{
    asm volatile(
        "mma.sync.aligned.m16n8k8.row.col.f32.tf32.tf32.f32 "
        "{%0,%1,%2,%3}, {%4,%5,%6,%7}, {%8,%9}, {%0,%1,%2,%3};"
        : "+f"(c[0]), "+f"(c[1]), "+f"(c[2]), "+f"(c[3])
        : "r"(a0), "r"(a1), "r"(a2), "r"(a3), "r"(b0), "r"(b1));
}

// ---------------- kernel 0: zero xbar ----------------
__global__ void zero_xbar_kernel() {
    g_xbar[blockIdx.x * 1024 + threadIdx.x] = 0.0f;
}

// ---------------- kernel 1: xbar = mean_S x ----------------
__global__ void mean_kernel(const float* __restrict__ x) {
    int b  = blockIdx.y;
    int d  = threadIdx.x;
    int s0 = blockIdx.x * 64;
    const float* xp = x + ((size_t)b * S_ + s0) * D_ + d;
    float acc = 0.0f;
    #pragma unroll 8
    for (int s = 0; s < 64; s++) acc += xp[(size_t)s * D_];
    atomicAdd(&g_xbar[b * D_ + d], acc * (1.0f / (float)S_));
}

// ---------------- kernel 2: router ----------------
__global__ void router_kernel(const float* __restrict__ Wr, const float* __restrict__ br,
                              const float* __restrict__ gamma, const float* __restrict__ beta) {
    int b = blockIdx.x;
    int w = threadIdx.x >> 5;
    int lane = threadIdx.x & 31;
    __shared__ float r_s[H_];
    const float* xb = g_xbar + b * D_;
    float acc = 0.0f;
    for (int d = lane; d < D_; d += 32)
        acc += xb[d] * Wr[d * H_ + w];
    #pragma unroll
    for (int off = 16; off; off >>= 1) acc += __shfl_xor_sync(0xffffffffu, acc, off);
    if (lane == 0) r_s[w] = acc + br[w];
    __syncthreads();
    if (threadIdx.x == 0) {
        float r[H_];
        for (int h = 0; h < H_; h++) r[h] = r_s[h];
        float mu = 0.f;
        for (int h = 0; h < H_; h++) mu += r[h];
        mu *= (1.0f / H_);
        float var = 0.f;
        for (int h = 0; h < H_; h++) { float dd = r[h] - mu; var += dd * dd; }
        var *= (1.0f / H_);
        float inv = rsqrtf(var + 1e-5f);
        float rn[H_];
        for (int h = 0; h < H_; h++) rn[h] = (r[h] - mu) * inv * gamma[h] + beta[h];
        float mx = rn[0];
        for (int h = 1; h < H_; h++) mx = fmaxf(mx, rn[h]);
        float e[H_]; float ssum = 0.f;
        for (int h = 0; h < H_; h++) { e[h] = expf(rn[h] - mx); ssum += e[h]; }
        float isum = 1.0f / ssum;
        for (int h = 0; h < H_; h++) e[h] *= isum;
        float tmp[H_];
        for (int h = 0; h < H_; h++) tmp[h] = e[h];
        int idx[A_];
        for (int j = 0; j < A_; j++) {
            int bi = 0; float bv = tmp[0];
            for (int h = 1; h < H_; h++) if (tmp[h] > bv) { bv = tmp[h]; bi = h; }
            idx[j] = bi; tmp[bi] = -1e30f;
        }
        for (int i = 0; i < A_; i++)
            for (int j = i + 1; j < A_; j++)
                if (idx[j] < idx[i]) { int t = idx[i]; idx[i] = idx[j]; idx[j] = t; }
        for (int j = 0; j < A_; j++) {
            g_idx [b * A_ + j] = idx[j];
            g_dist[b * A_ + j] = e[idx[j]];
        }
    }
}

// ---------------- kernel 3: gathered QKV projection (tf32 tensor cores) ----------------
__global__ __launch_bounds__(256) void qkv_gemm_tf32(
    const float* __restrict__ x,
    const float* __restrict__ Wq, const float* __restrict__ bq,
    const float* __restrict__ Wk, const float* __restrict__ bk,
    const float* __restrict__ Wv, const float* __restrict__ bv)
{
    int b     = blockIdx.z;
    int mt    = blockIdx.y;
    int which = blockIdx.x >> 1;
    int n0    = (blockIdx.x & 1) * 128;

    const float* W    = which == 0 ? Wq : (which == 1 ? Wk : Wv);
    const float* bias = which == 0 ? bq : (which == 1 ? bk : bv);
    float*       Out  = which == 0 ? g_Q : (which == 1 ? g_K : g_V);

    __shared__ float As[2][128][20];
    __shared__ float Bs[2][16][136];

    int tid  = threadIdx.x;
    int wid  = tid >> 5;
    int lane = tid & 31;
    int g    = lane >> 2, q = lane & 3;
    int wm   = (wid >> 2) * 64;
    int wn   = (wid & 3) * 32;

    int hc[2];
    hc[0] = g_idx[b * A_ + (n0 >> 6)    ] * 64;
    hc[1] = g_idx[b * A_ + (n0 >> 6) + 1] * 64;

    const float* xb = x + ((size_t)b * S_ + (size_t)mt * 128) * D_;

    float acc[4][4][4];
    #pragma unroll
    for (int mi = 0; mi < 4; mi++)
        #pragma unroll
        for (int ni = 0; ni < 4; ni++)
            #pragma unroll
            for (int c = 0; c < 4; c++) acc[mi][ni][c] = 0.f;

    float4 ra[2], rb[2];

    auto ldg_tile = [&](int k0) {
        #pragma unroll
        for (int i = 0; i < 2; i++) {
            int f   = tid + i * 256;
            int row = f >> 2, kc = (f & 3) * 4;
            ra[i] = *(const float4*)(xb + (size_t)row * D_ + k0 + kc);
        }
        #pragma unroll
        for (int i = 0; i < 2; i++) {
            int f   = tid + i * 256;
            int kk  = f >> 5, nn = (f & 31) * 4;
            int col = hc[nn >> 6] + (nn & 63);
            rb[i] = *(const float4*)(W + (size_t)(k0 + kk) * (H_ * DA_) + col);
        }
    };
    auto sts_tile = [&](int buf) {
        #pragma unroll
        for (int i = 0; i < 2; i++) {
            int f   = tid + i * 256;
            int row = f >> 2, kc = (f & 3) * 4;
            As[buf][row][kc + 0] = f2tf32(ra[i].x);
            As[buf][row][kc + 1] = f2tf32(ra[i].y);
            As[buf][row][kc + 2] = f2tf32(ra[i].z);
            As[buf][row][kc + 3] = f2tf32(ra[i].w);
        }
        #pragma unroll
        for (int i = 0; i < 2; i++) {
            int f  = tid + i * 256;
            int kk = f >> 5, nn = (f & 31) * 4;
            Bs[buf][kk][nn + 0] = f2tf32(rb[i].x);
            Bs[buf][kk][nn + 1] = f2tf32(rb[i].y);
            Bs[buf][kk][nn + 2] = f2tf32(rb[i].z);
            Bs[buf][kk][nn + 3] = f2tf32(rb[i].w);
        }
    };
    auto compute = [&](int buf) {
        #pragma unroll
        for (int kk = 0; kk < 16; kk += 8) {
            uint32_t afr[4][4], bfr[4][2];
            #pragma unroll
            for (int mi = 0; mi < 4; mi++) {
                int m = wm + mi * 16 + g;
                afr[mi][0] = __float_as_uint(As[buf][m    ][kk + q    ]);
                afr[mi][1] = __float_as_uint(As[buf][m + 8][kk + q    ]);
                afr[mi][2] = __float_as_uint(As[buf][m    ][kk + q + 4]);
                afr[mi][3] = __float_as_uint(As[buf][m + 8][kk + q + 4]);
            }
            #pragma unroll
            for (int ni = 0; ni < 4; ni++) {
                int n = wn + ni * 8 + g;
                bfr[ni][0] = __float_as_uint(Bs[buf][kk + q    ][n]);
                bfr[ni][1] = __float_as_uint(Bs[buf][kk + q + 4][n]);
            }
            #pragma unroll
            for (int mi = 0; mi < 4; mi++)
                #pragma unroll
                for (int ni = 0; ni < 4; ni++)
                    mma_tf32(acc[mi][ni], afr[mi][0], afr[mi][1], afr[mi][2], afr[mi][3],
                             bfr[ni][0], bfr[ni][1]);
        }
    };

    ldg_tile(0);
    sts_tile(0);
    __syncthreads();
    int buf = 0;
    for (int k0 = 16; k0 <= D_; k0 += 16) {
        bool has = (k0 < D_);
        if (has) ldg_tile(k0);
        compute(buf);
        if (has) sts_tile(buf ^ 1);
        __syncthreads();
        buf ^= 1;
    }

    #pragma unroll
    for (int mi = 0; mi < 4; mi++) {
        int m = mt * 128 + wm + mi * 16 + g;
        #pragma unroll
        for (int ni = 0; ni < 4; ni++) {
            int nn = wn + ni * 8 + q * 2;
            int hs = nn >> 6, d = nn & 63;
            int headslot = (n0 >> 6) + hs;
            float bz0 = bias[hc[hs] + d];
            float bz1 = bias[hc[hs] + d + 1];
            float* outp = Out + (((size_t)(b * A_ + headslot)) * S_) * DA_ + d;
            outp[(size_t)m * DA_ + 0]       = acc[mi][ni][0] + bz0;
            outp[(size_t)m * DA_ + 1]       = acc[mi][ni][1] + bz1;
            outp[(size_t)(m + 8) * DA_ + 0] = acc[mi][ni][2] + bz0;
            outp[(size_t)(m + 8) * DA_ + 1] = acc[mi][ni][3] + bz1;
        }
    }
}

// ---------------- kernel 4: flash attention on tf32 tensor cores ----------------
// grid (32 q-tiles of 64 rows, 32 (b,head) pairs), block 128 (4 warps).
// Each warp owns 16 q-rows and the full 128-col K tile (16 n-frags) -> softmax
// reductions stay inside a lane quad (shfl over q bits only).
// smem strides: Qs/Ks 68 (banks 4g+q distinct), Vs 72 (banks 8q+g distinct),
// Ps 132 aliases Ks.
#define QS_STRIDE 68
#define KS_STRIDE 68
#define VS_STRIDE 72
#define PS_STRIDE 132
#define QS_OFF    0
#define KS_OFF    (64 * QS_STRIDE)                 // 4352
#define VS_OFF    (KS_OFF + 128 * KS_STRIDE)       // 13056
#define ATTN_TC_SMEM_FLOATS (VS_OFF + 128 * VS_STRIDE)   // 22272 floats = 89088 B

__global__ __launch_bounds__(128) void attn_tc_kernel() {
    extern __shared__ float sm[];
    float* Qs = sm + QS_OFF;
    float* Ks = sm + KS_OFF;
    float* Ps = sm + KS_OFF;        // alias: P overwrites K tile after QK^T
    float* Vs = sm + VS_OFF;

    int qt  = blockIdx.x;
    int bj  = blockIdx.y;
    int b   = bj >> 2, js = bj & 3;
    int tid = threadIdx.x;
    int wid  = tid >> 5;
    int lane = tid & 31;
    int g = lane >> 2, q = lane & 3;
    int wm = wid * 16;                    // warp's 16-row strip in the 64-row q-tile
    unsigned qmask = 0xffffffffu;

    const float* Qg = g_Q + (size_t)bj * S_ * DA_ + (size_t)qt * 64 * DA_;
    const float* Kg = g_K + (size_t)bj * S_ * DA_;
    const float* Vg = g_V + (size_t)bj * S_ * DA_;

    // ---- load Q tile (64 x 64) ----
    #pragma unroll
    for (int i = 0; i < 8; i++) {
        int f = tid + i * 128;
        int r = f >> 4, c = (f & 15) * 4;
        float4 v = ((const float4*)Qg)[f];
        Qs[r * QS_STRIDE + c + 0] = f2tf32(v.x);
        Qs[r * QS_STRIDE + c + 1] = f2tf32(v.y);
        Qs[r * QS_STRIDE + c + 2] = f2tf32(v.z);
        Qs[r * QS_STRIDE + c + 3] = f2tf32(v.w);
    }

    float Sfr[16][4];
    float Ofr[8][4];
    #pragma unroll
    for (int i = 0; i < 8; i++)
        #pragma unroll
        for (int c = 0; c < 4; c++) Ofr[i][c] = 0.f;
    float m0 = -1e30f, m1 = -1e30f, l0 = 0.f, l1 = 0.f;

    for (int t = 0; t < 16; t++) {
        __syncthreads();   // prev iter PV done reading Vs/Ps; Q fill covered on t=0
        // ---- fill K,V tiles (128 x 64 each) ----
        const float4* Kt = (const float4*)(Kg + (size_t)t * 128 * DA_);
        const float4* Vt = (const float4*)(Vg + (size_t)t * 128 * DA_);
        #pragma unroll
        for (int i = 0; i < 16; i++) {
            int f = tid + i * 128;
            int r = f >> 4, c = (f & 15) * 4;
            float4 kv = Kt[f];
            Ks[r * KS_STRIDE + c + 0] = f2tf32(kv.x);
            Ks[r * KS_STRIDE + c + 1] = f2tf32(kv.y);
            Ks[r * KS_STRIDE + c + 2] = f2tf32(kv.z);
            Ks[r * KS_STRIDE + c + 3] = f2tf32(kv.w);
            float4 vv = Vt[f];
            Vs[r * VS_STRIDE + c + 0] = f2tf32(vv.x);
            Vs[r * VS_STRIDE + c + 1] = f2tf32(vv.y);
            Vs[r * VS_STRIDE + c + 2] = f2tf32(vv.z);
            Vs[r * VS_STRIDE + c + 3] = f2tf32(vv.w);
        }
        __syncthreads();

        // ---- S = Q @ K^T  (warp: 16 rows x 128 cols) ----
        #pragma unroll
        for (int ni = 0; ni < 16; ni++)
            #pragma unroll
            for (int c = 0; c < 4; c++) Sfr[ni][c] = 0.f;

        #pragma unroll
        for (int ks = 0; ks < 8; ks++) {
            int kk = ks * 8;
            uint32_t a0 = __float_as_uint(Qs[(wm + g    ) * QS_STRIDE + kk + q    ]);
            uint32_t a1 = __float_as_uint(Qs[(wm + g + 8) * QS_STRIDE + kk + q    ]);
            uint32_t a2 = __float_as_uint(Qs[(wm + g    ) * QS_STRIDE + kk + q + 4]);
            uint32_t a3 = __float_as_uint(Qs[(wm + g + 8) * QS_STRIDE + kk + q + 4]);
            #pragma unroll
            for (int ni = 0; ni < 16; ni++) {
                int n = ni * 8 + g;
                uint32_t b0 = __float_as_uint(Ks[n * KS_STRIDE + kk + q    ]);
                uint32_t b1 = __float_as_uint(Ks[n * KS_STRIDE + kk + q + 4]);
                mma_tf32(Sfr[ni], a0, a1, a2, a3, b0, b1);
            }
        }

        // ---- online softmax (rows wm+g, wm+g+8; quad reduce over q) ----
        float mx0 = -1e30f, mx1 = -1e30f;
        #pragma unroll
        for (int ni = 0; ni < 16; ni++) {
            mx0 = fmaxf(mx0, fmaxf(Sfr[ni][0], Sfr[ni][1]));
            mx1 = fmaxf(mx1, fmaxf(Sfr[ni][2], Sfr[ni][3]));
        }
        mx0 = fmaxf(mx0, __shfl_xor_sync(qmask, mx0, 1));
        mx0 = fmaxf(mx0, __shfl_xor_sync(qmask, mx0, 2));
        mx1 = fmaxf(mx1, __shfl_xor_sync(qmask, mx1, 1));
        mx1 = fmaxf(mx1, __shfl_xor_sync(qmask, mx1, 2));
        mx0 *= 0.125f; mx1 *= 0.125f;   // scale applied after max (monotone)
        float mn0 = fmaxf(m0, mx0), mn1 = fmaxf(m1, mx1);
        float cr0 = __expf(m0 - mn0), cr1 = __expf(m1 - mn1);
        float ts0 = 0.f, ts1 = 0.f;
        #pragma unroll
        for (int ni = 0; ni < 16; ni++) {
            float p0 = __expf(Sfr[ni][0] * 0.125f - mn0);
            float p1 = __expf(Sfr[ni][1] * 0.125f - mn0);
            float p2 = __expf(Sfr[ni][2] * 0.125f - mn1);
            float p3 = __expf(Sfr[ni][3] * 0.125f - mn1);
            Sfr[ni][0] = p0; Sfr[ni][1] = p1; Sfr[ni][2] = p2; Sfr[ni][3] = p3;
            ts0 += p0 + p1; ts1 += p2 + p3;
        }
        ts0 += __shfl_xor_sync(qmask, ts0, 1);
        ts0 += __shfl_xor_sync(qmask, ts0, 2);
        ts1 += __shfl_xor_sync(qmask, ts1, 1);
        ts1 += __shfl_xor_sync(qmask, ts1, 2);
        l0 = l0 * cr0 + ts0;  m0 = mn0;
        l1 = l1 * cr1 + ts1;  m1 = mn1;
        #pragma unroll
        for (int i = 0; i < 8; i++) {
            Ofr[i][0] *= cr0; Ofr[i][1] *= cr0;
            Ofr[i][2] *= cr1; Ofr[i][3] *= cr1;
        }

        __syncthreads();   // all warps done reading Ks before P overwrites it

        // ---- write P (aliases Ks) ----
        #pragma unroll
        for (int ni = 0; ni < 16; ni++) {
            float2 p01; p01.x = f2tf32(Sfr[ni][0]); p01.y = f2tf32(Sfr[ni][1]);
            float2 p23; p23.x = f2tf32(Sfr[ni][2]); p23.y = f2tf32(Sfr[ni][3]);
            *(float2*)&Ps[(wm + g    ) * PS_STRIDE + ni * 8 + 2 * q] = p01;
            *(float2*)&Ps[(wm + g + 8) * PS_STRIDE + ni * 8 + 2 * q] = p23;
        }
        __syncwarp();       // warp reads back only its own 16 rows

        // ---- O += P @ V  (warp: 16 rows x 64 d-cols) ----
        #pragma unroll
        for (int ks = 0; ks < 16; ks++) {
            int kk = ks * 8;
            uint32_t a0 = __float_as_uint(Ps[(wm + g    ) * PS_STRIDE + kk + q    ]);
            uint32_t a1 = __float_as_uint(Ps[(wm + g + 8) * PS_STRIDE + kk + q    ]);
            uint32_t a2 = __float_as_uint(Ps[(wm + g    ) * PS_STRIDE + kk + q + 4]);
            uint32_t a3 = __float_as_uint(Ps[(wm + g + 8) * PS_STRIDE + kk + q + 4]);
            #pragma unroll
            for (int ni = 0; ni < 8; ni++) {
                int n = ni * 8 + g;
                uint32_t b0 = __float_as_uint(Vs[(kk + q    ) * VS_STRIDE + n]);
                uint32_t b1 = __float_as_uint(Vs[(kk + q + 4) * VS_STRIDE + n]);
                mma_tf32(Ofr[ni], a0, a1, a2, a3, b0, b1);
            }
        }
    }

    // ---- epilogue: scale by dist/l, store ----
    float dist = g_dist[b * A_ + js];
    float sc0 = dist / l0, sc1 = dist / l1;
    int r0 = qt * 64 + wm + g, r1 = r0 + 8;
    float* z0 = g_O + ((size_t)(b * S_ + r0)) * (A_ * DA_) + js * 64;
    float* z1 = g_O + ((size_t)(b * S_ + r1)) * (A_ * DA_) + js * 64;
    #pragma unroll
    for (int ni = 0; ni < 8; ni++) {
        int c = ni * 8 + 2 * q;
        float2 v0; v0.x = Ofr[ni][0] * sc0; v0.y = Ofr[ni][1] * sc0;
        float2 v1; v1.x = Ofr[ni][2] * sc1; v1.y = Ofr[ni][3] * sc1;
        *(float2*)&z0[c] = v0;
        *(float2*)&z1[c] = v1;
    }
}

// ---------------- kernel 5: Z = O_final @ Wo + bo (tf32 tensor cores) ----------------
__global__ __launch_bounds__(256) void out_gemm_tf32(
    const float* __restrict__ Wo, const float* __restrict__ bo,
    float* __restrict__ Z)
{
    int m0 = blockIdx.y * 128;
    int n0 = blockIdx.x * 128;

    __shared__ float As[2][128][20];
    __shared__ float Bs[2][16][136];

    int tid  = threadIdx.x;
    int wid  = tid >> 5;
    int lane = tid & 31;
    int g    = lane >> 2, q = lane & 3;
    int wm   = (wid >> 2) * 64;
    int wn   = (wid & 3) * 32;

    float acc[4][4][4];
    #pragma unroll
    for (int mi = 0; mi < 4; mi++)
        #pragma unroll
        for (int ni = 0; ni < 4; ni++)
            #pragma unroll
            for (int c = 0; c < 4; c++) acc[mi][ni][c] = 0.f;

    float4 ra[2], rb[2];

    auto ldg_tile = [&](int k0) {
        #pragma unroll
        for (int i = 0; i < 2; i++) {
            int f   = tid + i * 256;
            int row = f >> 2, kc = (f & 3) * 4;
            ra[i] = *(const float4*)(g_O + (size_t)(m0 + row) * (A_ * DA_) + k0 + kc);
        }
        #pragma unroll
        for (int i = 0; i < 2; i++) {
            int f  = tid + i * 256;
            int kk = f >> 5, nn = (f & 31) * 4;
            rb[i] = *(const float4*)(Wo + (size_t)(k0 + kk) * D_ + n0 + nn);
        }
    };
    auto sts_tile = [&](int buf) {
        #pragma unroll
        for (int i = 0; i < 2; i++) {
            int f   = tid + i * 256;
            int row = f >> 2, kc = (f & 3) * 4;
            As[buf][row][kc + 0] = f2tf32(ra[i].x);
            As[buf][row][kc + 1] = f2tf32(ra[i].y);
            As[buf][row][kc + 2] = f2tf32(ra[i].z);
            As[buf][row][kc + 3] = f2tf32(ra[i].w);
        }
        #pragma unroll
        for (int i = 0; i < 2; i++) {
            int f  = tid + i * 256;
            int kk = f >> 5, nn = (f & 31) * 4;
            Bs[buf][kk][nn + 0] = f2tf32(rb[i].x);
            Bs[buf][kk][nn + 1] = f2tf32(rb[i].y);
            Bs[buf][kk][nn + 2] = f2tf32(rb[i].z);
            Bs[buf][kk][nn + 3] = f2tf32(rb[i].w);
        }
    };
    auto compute = [&](int buf) {
        #pragma unroll
        for (int kk = 0; kk < 16; kk += 8) {
            uint32_t afr[4][4], bfr[4][2];
            #pragma unroll
            for (int mi = 0; mi < 4; mi++) {
                int m = wm + mi * 16 + g;
                afr[mi][0] = __float_as_uint(As[buf][m    ][kk + q    ]);
                afr[mi][1] = __float_as_uint(As[buf][m + 8][kk + q    ]);
                afr[mi][2] = __float_as_uint(As[buf][m    ][kk + q + 4]);
                afr[mi][3] = __float_as_uint(As[buf][m + 8][kk + q + 4]);
            }
            #pragma unroll
            for (int ni = 0; ni < 4; ni++) {
                int n = wn + ni * 8 + g;
                bfr[ni][0] = __float_as_uint(Bs[buf][kk + q    ][n]);
                bfr[ni][1] = __float_as_uint(Bs[buf][kk + q + 4][n]);
            }
            #pragma unroll
            for (int mi = 0; mi < 4; mi++)
                #pragma unroll
                for (int ni = 0; ni < 4; ni++)
                    mma_tf32(acc[mi][ni], afr[mi][0], afr[mi][1], afr[mi][2], afr[mi][3],
                             bfr[ni][0], bfr[ni][1]);
        }
    };

    ldg_tile(0);
    sts_tile(0);
    __syncthreads();
    int buf = 0;
    for (int k0 = 16; k0 <= A_ * DA_; k0 += 16) {
        bool has = (k0 < A_ * DA_);
        if (has) ldg_tile(k0);
        compute(buf);
        if (has) sts_tile(buf ^ 1);
        __syncthreads();
        buf ^= 1;
    }

    #pragma unroll
    for (int mi = 0; mi < 4; mi++) {
        int m = m0 + wm + mi * 16 + g;
        #pragma unroll
        for (int ni = 0; ni < 4; ni++) {
            int n = n0 + wn + ni * 8 + q * 2;
            float b0v = bo[n], b1v = bo[n + 1];
            Z[(size_t)m * D_ + n]           = acc[mi][ni][0] + b0v;
            Z[(size_t)m * D_ + n + 1]       = acc[mi][ni][1] + b1v;
            Z[(size_t)(m + 8) * D_ + n]     = acc[mi][ni][2] + b0v;
            Z[(size_t)(m + 8) * D_ + n + 1] = acc[mi][ni][3] + b1v;
        }
    }
}

// ---------------- launch ----------------
extern "C" void kernel_launch(void* const* d_in, const int* in_sizes, int n_in,
                              void* d_out, int out_size) {
    const float* x     = (const float*)d_in[0];
    const float* Wq    = (const float*)d_in[1];
    const float* bq    = (const float*)d_in[2];
    const float* Wk    = (const float*)d_in[3];
    const float* bk    = (const float*)d_in[4];
    const float* Wv    = (const float*)d_in[5];
    const float* bv    = (const float*)d_in[6];
    const float* Wr    = (const float*)d_in[7];
    const float* br    = (const float*)d_in[8];
    const float* gamma = (const float*)d_in[9];
    const float* beta  = (const float*)d_in[10];
    const float* Wo    = (const float*)d_in[11];
    const float* bo    = (const float*)d_in[12];
    float* Z = (float*)d_out;

    cudaFuncSetAttribute(attn_tc_kernel, cudaFuncAttributeMaxDynamicSharedMemorySize,
                         ATTN_TC_SMEM_FLOATS * (int)sizeof(float));

    zero_xbar_kernel<<<B_, 1024>>>();
    mean_kernel<<<dim3(32, B_), 1024>>>(x);
    router_kernel<<<B_, 512>>>(Wr, br, gamma, beta);
    qkv_gemm_tf32<<<dim3(6, 16, B_), 256>>>(x, Wq, bq, Wk, bk, Wv, bv);
    attn_tc_kernel<<<dim3(32, 32), 128, ATTN_TC_SMEM_FLOATS * (int)sizeof(float)>>>();
    out_gemm_tf32<<<dim3(8, 128), 256>>>(Wo, bo, Z);
}

// round 12
// speedup vs baseline: 2.9400x; 1.7645x over previous
#include <cuda_runtime.h>
#include <math.h>
#include <stdint.h>

#define B_  8
#define S_  2048
#define D_  1024
#define H_  16
#define A_  4
#define DA_ 64

// ---------------- scratch (static device memory; no allocation) ----------------
__device__ float g_xbar[B_ * D_];
__device__ float g_dist[B_ * A_];
__device__ int   g_idx [B_ * A_];
__device__ float g_Q[(size_t)B_ * A_ * S_ * DA_];   // (b*4+j, s, d)
__device__ float g_K[(size_t)B_ * A_ * S_ * DA_];
__device__ float g_V[(size_t)B_ * A_ * S_ * DA_];
__device__ float g_O[(size_t)B_ * S_ * A_ * DA_];   // (b*S+s, j*64+d)

// ---------------- helpers ----------------
__device__ __forceinline__ float f2tf32(float x) {
    asm("cvt.rna.tf32.f32 %0, %0;" : "+f"(x));
    return x;
}

__device__ __forceinline__ void mma_tf32(float* c,
    uint32_t a0, uint32_t a1, uint32_t a2, uint32_t a3,
    uint32_t b0, uint32_t b1)
{
    asm volatile(
        "mma.sync.aligned.m16n8k8.row.col.f32.tf32.tf32.f32 "
        "{%0,%1,%2,%3}, {%4,%5,%6,%7}, {%8,%9}, {%0,%1,%2,%3};"
        : "+f"(c[0]), "+f"(c[1]), "+f"(c[2]), "+f"(c[3])
        : "r"(a0), "r"(a1), "r"(a2), "r"(a3), "r"(b0), "r"(b1));
}

// ---------------- kernel 0: zero xbar ----------------
__global__ void zero_xbar_kernel() {
    g_xbar[blockIdx.x * 1024 + threadIdx.x] = 0.0f;
}

// ---------------- kernel 1: xbar = mean_S x ----------------
__global__ void mean_kernel(const float* __restrict__ x) {
    int b  = blockIdx.y;
    int d  = threadIdx.x;
    int s0 = blockIdx.x * 64;
    const float* xp = x + ((size_t)b * S_ + s0) * D_ + d;
    float acc = 0.0f;
    #pragma unroll 8
    for (int s = 0; s < 64; s++) acc += xp[(size_t)s * D_];
    atomicAdd(&g_xbar[b * D_ + d], acc * (1.0f / (float)S_));
}

// ---------------- kernel 2: router ----------------
__global__ void router_kernel(const float* __restrict__ Wr, const float* __restrict__ br,
                              const float* __restrict__ gamma, const float* __restrict__ beta) {
    int b = blockIdx.x;
    int w = threadIdx.x >> 5;
    int lane = threadIdx.x & 31;
    __shared__ float r_s[H_];
    const float* xb = g_xbar + b * D_;
    float acc = 0.0f;
    for (int d = lane; d < D_; d += 32)
        acc += xb[d] * Wr[d * H_ + w];
    #pragma unroll
    for (int off = 16; off; off >>= 1) acc += __shfl_xor_sync(0xffffffffu, acc, off);
    if (lane == 0) r_s[w] = acc + br[w];
    __syncthreads();
    if (threadIdx.x == 0) {
        float r[H_];
        for (int h = 0; h < H_; h++) r[h] = r_s[h];
        float mu = 0.f;
        for (int h = 0; h < H_; h++) mu += r[h];
        mu *= (1.0f / H_);
        float var = 0.f;
        for (int h = 0; h < H_; h++) { float dd = r[h] - mu; var += dd * dd; }
        var *= (1.0f / H_);
        float inv = rsqrtf(var + 1e-5f);
        float rn[H_];
        for (int h = 0; h < H_; h++) rn[h] = (r[h] - mu) * inv * gamma[h] + beta[h];
        float mx = rn[0];
        for (int h = 1; h < H_; h++) mx = fmaxf(mx, rn[h]);
        float e[H_]; float ssum = 0.f;
        for (int h = 0; h < H_; h++) { e[h] = expf(rn[h] - mx); ssum += e[h]; }
        float isum = 1.0f / ssum;
        for (int h = 0; h < H_; h++) e[h] *= isum;
        float tmp[H_];
        for (int h = 0; h < H_; h++) tmp[h] = e[h];
        int idx[A_];
        for (int j = 0; j < A_; j++) {
            int bi = 0; float bv = tmp[0];
            for (int h = 1; h < H_; h++) if (tmp[h] > bv) { bv = tmp[h]; bi = h; }
            idx[j] = bi; tmp[bi] = -1e30f;
        }
        for (int i = 0; i < A_; i++)
            for (int j = i + 1; j < A_; j++)
                if (idx[j] < idx[i]) { int t = idx[i]; idx[i] = idx[j]; idx[j] = t; }
        for (int j = 0; j < A_; j++) {
            g_idx [b * A_ + j] = idx[j];
            g_dist[b * A_ + j] = e[idx[j]];
        }
    }
}

// ---------------- kernel 3: gathered QKV projection (tf32 tensor cores) ----------------
// __launch_bounds__(256, 2): force regs <= 128 for 2 blocks/SM (occupancy experiment)
__global__ __launch_bounds__(256, 2) void qkv_gemm_tf32(
    const float* __restrict__ x,
    const float* __restrict__ Wq, const float* __restrict__ bq,
    const float* __restrict__ Wk, const float* __restrict__ bk,
    const float* __restrict__ Wv, const float* __restrict__ bv)
{
    int b     = blockIdx.z;
    int mt    = blockIdx.y;
    int which = blockIdx.x >> 1;
    int n0    = (blockIdx.x & 1) * 128;

    const float* W    = which == 0 ? Wq : (which == 1 ? Wk : Wv);
    const float* bias = which == 0 ? bq : (which == 1 ? bk : bv);
    float*       Out  = which == 0 ? g_Q : (which == 1 ? g_K : g_V);

    __shared__ float As[2][128][20];
    __shared__ float Bs[2][16][136];

    int tid  = threadIdx.x;
    int wid  = tid >> 5;
    int lane = tid & 31;
    int g    = lane >> 2, q = lane & 3;
    int wm   = (wid >> 2) * 64;
    int wn   = (wid & 3) * 32;

    int hc[2];
    hc[0] = g_idx[b * A_ + (n0 >> 6)    ] * 64;
    hc[1] = g_idx[b * A_ + (n0 >> 6) + 1] * 64;

    const float* xb = x + ((size_t)b * S_ + (size_t)mt * 128) * D_;

    float acc[4][4][4];
    #pragma unroll
    for (int mi = 0; mi < 4; mi++)
        #pragma unroll
        for (int ni = 0; ni < 4; ni++)
            #pragma unroll
            for (int c = 0; c < 4; c++) acc[mi][ni][c] = 0.f;

    float4 ra[2], rb[2];

    auto ldg_tile = [&](int k0) {
        #pragma unroll
        for (int i = 0; i < 2; i++) {
            int f   = tid + i * 256;
            int row = f >> 2, kc = (f & 3) * 4;
            ra[i] = *(const float4*)(xb + (size_t)row * D_ + k0 + kc);
        }
        #pragma unroll
        for (int i = 0; i < 2; i++) {
            int f   = tid + i * 256;
            int kk  = f >> 5, nn = (f & 31) * 4;
            int col = hc[nn >> 6] + (nn & 63);
            rb[i] = *(const float4*)(W + (size_t)(k0 + kk) * (H_ * DA_) + col);
        }
    };
    auto sts_tile = [&](int buf) {
        #pragma unroll
        for (int i = 0; i < 2; i++) {
            int f   = tid + i * 256;
            int row = f >> 2, kc = (f & 3) * 4;
            As[buf][row][kc + 0] = f2tf32(ra[i].x);
            As[buf][row][kc + 1] = f2tf32(ra[i].y);
            As[buf][row][kc + 2] = f2tf32(ra[i].z);
            As[buf][row][kc + 3] = f2tf32(ra[i].w);
        }
        #pragma unroll
        for (int i = 0; i < 2; i++) {
            int f  = tid + i * 256;
            int kk = f >> 5, nn = (f & 31) * 4;
            Bs[buf][kk][nn + 0] = f2tf32(rb[i].x);
            Bs[buf][kk][nn + 1] = f2tf32(rb[i].y);
            Bs[buf][kk][nn + 2] = f2tf32(rb[i].z);
            Bs[buf][kk][nn + 3] = f2tf32(rb[i].w);
        }
    };
    auto compute = [&](int buf) {
        #pragma unroll
        for (int kk = 0; kk < 16; kk += 8) {
            uint32_t afr[4][4], bfr[4][2];
            #pragma unroll
            for (int mi = 0; mi < 4; mi++) {
                int m = wm + mi * 16 + g;
                afr[mi][0] = __float_as_uint(As[buf][m    ][kk + q    ]);
                afr[mi][1] = __float_as_uint(As[buf][m + 8][kk + q    ]);
                afr[mi][2] = __float_as_uint(As[buf][m    ][kk + q + 4]);
                afr[mi][3] = __float_as_uint(As[buf][m + 8][kk + q + 4]);
            }
            #pragma unroll
            for (int ni = 0; ni < 4; ni++) {
                int n = wn + ni * 8 + g;
                bfr[ni][0] = __float_as_uint(Bs[buf][kk + q    ][n]);
                bfr[ni][1] = __float_as_uint(Bs[buf][kk + q + 4][n]);
            }
            #pragma unroll
            for (int mi = 0; mi < 4; mi++)
                #pragma unroll
                for (int ni = 0; ni < 4; ni++)
                    mma_tf32(acc[mi][ni], afr[mi][0], afr[mi][1], afr[mi][2], afr[mi][3],
                             bfr[ni][0], bfr[ni][1]);
        }
    };

    ldg_tile(0);
    sts_tile(0);
    __syncthreads();
    int buf = 0;
    for (int k0 = 16; k0 <= D_; k0 += 16) {
        bool has = (k0 < D_);
        if (has) ldg_tile(k0);
        compute(buf);
        if (has) sts_tile(buf ^ 1);
        __syncthreads();
        buf ^= 1;
    }

    #pragma unroll
    for (int mi = 0; mi < 4; mi++) {
        int m = mt * 128 + wm + mi * 16 + g;
        #pragma unroll
        for (int ni = 0; ni < 4; ni++) {
            int nn = wn + ni * 8 + q * 2;
            int hs = nn >> 6, d = nn & 63;
            int headslot = (n0 >> 6) + hs;
            float bz0 = bias[hc[hs] + d];
            float bz1 = bias[hc[hs] + d + 1];
            float* outp = Out + (((size_t)(b * A_ + headslot)) * S_) * DA_ + d;
            outp[(size_t)m * DA_ + 0]       = acc[mi][ni][0] + bz0;
            outp[(size_t)m * DA_ + 1]       = acc[mi][ni][1] + bz1;
            outp[(size_t)(m + 8) * DA_ + 0] = acc[mi][ni][2] + bz0;
            outp[(size_t)(m + 8) * DA_ + 1] = acc[mi][ni][3] + bz1;
        }
    }
}

// ---------------- kernel 4: flash attention on tf32 tensor cores ----------------
// grid (16 q-tiles of 128 rows, 32 (b,head) pairs), block 256 (8 warps).
// Each warp owns a 16-row q-strip and the full 128-col K tile -> softmax stays
// quad-local (same warp math as the proven 4-warp version).
// PV is phase-split over k (0..63, 64..127) so P (128 x 68) exactly aliases Ks.
// P reads are warp-private rows -> phases need only __syncwarp.
// smem: Qs 128x68 | Ks/Ps 128x68 | Vs 128x72 = 26624 floats = 104 KB -> 2 blocks/SM.
#define QS_STRIDE 68
#define KS_STRIDE 68
#define VS_STRIDE 72
#define QS_OFF    0
#define KS_OFF    (128 * QS_STRIDE)                // 8704
#define VS_OFF    (KS_OFF + 128 * KS_STRIDE)       // 17408
#define ATTN_TC_SMEM_FLOATS (VS_OFF + 128 * VS_STRIDE)   // 26624 floats = 106496 B

__global__ __launch_bounds__(256) void attn_tc_kernel() {
    extern __shared__ float sm[];
    float* Qs = sm + QS_OFF;
    float* Ks = sm + KS_OFF;
    float* Ps = sm + KS_OFF;        // alias: P overwrites K tile after QK^T
    float* Vs = sm + VS_OFF;

    int qt  = blockIdx.x;
    int bj  = blockIdx.y;
    int b   = bj >> 2, js = bj & 3;
    int tid = threadIdx.x;
    int wid  = tid >> 5;
    int lane = tid & 31;
    int g = lane >> 2, q = lane & 3;
    int wm = wid * 16;                    // warp's 16-row strip in the 128-row q-tile
    unsigned qmask = 0xffffffffu;

    const float* Qg = g_Q + (size_t)bj * S_ * DA_ + (size_t)qt * 128 * DA_;
    const float* Kg = g_K + (size_t)bj * S_ * DA_;
    const float* Vg = g_V + (size_t)bj * S_ * DA_;

    // ---- load Q tile (128 x 64) ----
    #pragma unroll
    for (int i = 0; i < 8; i++) {
        int f = tid + i * 256;
        int r = f >> 4, c = (f & 15) * 4;
        float4 v = ((const float4*)Qg)[f];
        Qs[r * QS_STRIDE + c + 0] = f2tf32(v.x);
        Qs[r * QS_STRIDE + c + 1] = f2tf32(v.y);
        Qs[r * QS_STRIDE + c + 2] = f2tf32(v.z);
        Qs[r * QS_STRIDE + c + 3] = f2tf32(v.w);
    }

    float Sfr[16][4];
    float Ofr[8][4];
    #pragma unroll
    for (int i = 0; i < 8; i++)
        #pragma unroll
        for (int c = 0; c < 4; c++) Ofr[i][c] = 0.f;
    float m0 = -1e30f, m1 = -1e30f, l0 = 0.f, l1 = 0.f;

    for (int t = 0; t < 16; t++) {
        __syncthreads();   // prev iter PV done reading Ps/Vs; Q fill covered on t=0
        // ---- fill K,V tiles (128 x 64 each) ----
        const float4* Kt = (const float4*)(Kg + (size_t)t * 128 * DA_);
        const float4* Vt = (const float4*)(Vg + (size_t)t * 128 * DA_);
        #pragma unroll
        for (int i = 0; i < 8; i++) {
            int f = tid + i * 256;
            int r = f >> 4, c = (f & 15) * 4;
            float4 kv = Kt[f];
            Ks[r * KS_STRIDE + c + 0] = f2tf32(kv.x);
            Ks[r * KS_STRIDE + c + 1] = f2tf32(kv.y);
            Ks[r * KS_STRIDE + c + 2] = f2tf32(kv.z);
            Ks[r * KS_STRIDE + c + 3] = f2tf32(kv.w);
            float4 vv = Vt[f];
            Vs[r * VS_STRIDE + c + 0] = f2tf32(vv.x);
            Vs[r * VS_STRIDE + c + 1] = f2tf32(vv.y);
            Vs[r * VS_STRIDE + c + 2] = f2tf32(vv.z);
            Vs[r * VS_STRIDE + c + 3] = f2tf32(vv.w);
        }
        __syncthreads();

        // ---- S = Q @ K^T  (warp: 16 rows x 128 cols) ----
        #pragma unroll
        for (int ni = 0; ni < 16; ni++)
            #pragma unroll
            for (int c = 0; c < 4; c++) Sfr[ni][c] = 0.f;

        #pragma unroll
        for (int ks = 0; ks < 8; ks++) {
            int kk = ks * 8;
            uint32_t a0 = __float_as_uint(Qs[(wm + g    ) * QS_STRIDE + kk + q    ]);
            uint32_t a1 = __float_as_uint(Qs[(wm + g + 8) * QS_STRIDE + kk + q    ]);
            uint32_t a2 = __float_as_uint(Qs[(wm + g    ) * QS_STRIDE + kk + q + 4]);
            uint32_t a3 = __float_as_uint(Qs[(wm + g + 8) * QS_STRIDE + kk + q + 4]);
            #pragma unroll
            for (int ni = 0; ni < 16; ni++) {
                int n = ni * 8 + g;
                uint32_t b0 = __float_as_uint(Ks[n * KS_STRIDE + kk + q    ]);
                uint32_t b1 = __float_as_uint(Ks[n * KS_STRIDE + kk + q + 4]);
                mma_tf32(Sfr[ni], a0, a1, a2, a3, b0, b1);
            }
        }

        // ---- online softmax (rows wm+g, wm+g+8; quad reduce over q) ----
        float mx0 = -1e30f, mx1 = -1e30f;
        #pragma unroll
        for (int ni = 0; ni < 16; ni++) {
            mx0 = fmaxf(mx0, fmaxf(Sfr[ni][0], Sfr[ni][1]));
            mx1 = fmaxf(mx1, fmaxf(Sfr[ni][2], Sfr[ni][3]));
        }
        mx0 = fmaxf(mx0, __shfl_xor_sync(qmask, mx0, 1));
        mx0 = fmaxf(mx0, __shfl_xor_sync(qmask, mx0, 2));
        mx1 = fmaxf(mx1, __shfl_xor_sync(qmask, mx1, 1));
        mx1 = fmaxf(mx1, __shfl_xor_sync(qmask, mx1, 2));
        mx0 *= 0.125f; mx1 *= 0.125f;   // scale applied after max (monotone)
        float mn0 = fmaxf(m0, mx0), mn1 = fmaxf(m1, mx1);
        float cr0 = __expf(m0 - mn0), cr1 = __expf(m1 - mn1);
        float ts0 = 0.f, ts1 = 0.f;
        #pragma unroll
        for (int ni = 0; ni < 16; ni++) {
            float p0 = __expf(Sfr[ni][0] * 0.125f - mn0);
            float p1 = __expf(Sfr[ni][1] * 0.125f - mn0);
            float p2 = __expf(Sfr[ni][2] * 0.125f - mn1);
            float p3 = __expf(Sfr[ni][3] * 0.125f - mn1);
            Sfr[ni][0] = p0; Sfr[ni][1] = p1; Sfr[ni][2] = p2; Sfr[ni][3] = p3;
            ts0 += p0 + p1; ts1 += p2 + p3;
        }
        ts0 += __shfl_xor_sync(qmask, ts0, 1);
        ts0 += __shfl_xor_sync(qmask, ts0, 2);
        ts1 += __shfl_xor_sync(qmask, ts1, 1);
        ts1 += __shfl_xor_sync(qmask, ts1, 2);
        l0 = l0 * cr0 + ts0;  m0 = mn0;
        l1 = l1 * cr1 + ts1;  m1 = mn1;
        #pragma unroll
        for (int i = 0; i < 8; i++) {
            Ofr[i][0] *= cr0; Ofr[i][1] *= cr0;
            Ofr[i][2] *= cr1; Ofr[i][3] *= cr1;
        }

        __syncthreads();   // all warps done reading Ks before P overwrites it

        // ---- PV in two phases; P buffer holds 64 k-cols at a time ----
        #pragma unroll
        for (int ph = 0; ph < 2; ph++) {
            // write P cols [ph*64, ph*64+64) into Ps (stride 68), warp-private rows
            #pragma unroll
            for (int ni = 0; ni < 8; ni++) {
                int nig = ph * 8 + ni;
                float2 p01; p01.x = f2tf32(Sfr[nig][0]); p01.y = f2tf32(Sfr[nig][1]);
                float2 p23; p23.x = f2tf32(Sfr[nig][2]); p23.y = f2tf32(Sfr[nig][3]);
                *(float2*)&Ps[(wm + g    ) * KS_STRIDE + ni * 8 + 2 * q] = p01;
                *(float2*)&Ps[(wm + g + 8) * KS_STRIDE + ni * 8 + 2 * q] = p23;
            }
            __syncwarp();   // warp reads back only its own 16 rows

            // O += P_phase @ V_phase  (V rows ph*64 .. ph*64+63)
            #pragma unroll
            for (int ks = 0; ks < 8; ks++) {
                int kk = ks * 8;
                uint32_t a0 = __float_as_uint(Ps[(wm + g    ) * KS_STRIDE + kk + q    ]);
                uint32_t a1 = __float_as_uint(Ps[(wm + g + 8) * KS_STRIDE + kk + q    ]);
                uint32_t a2 = __float_as_uint(Ps[(wm + g    ) * KS_STRIDE + kk + q + 4]);
                uint32_t a3 = __float_as_uint(Ps[(wm + g + 8) * KS_STRIDE + kk + q + 4]);
                int vr = ph * 64 + kk;
                #pragma unroll
                for (int ni = 0; ni < 8; ni++) {
                    int n = ni * 8 + g;
                    uint32_t b0 = __float_as_uint(Vs[(vr + q    ) * VS_STRIDE + n]);
                    uint32_t b1 = __float_as_uint(Vs[(vr + q + 4) * VS_STRIDE + n]);
                    mma_tf32(Ofr[ni], a0, a1, a2, a3, b0, b1);
                }
            }
            __syncwarp();   // phase-2 P write must not race phase-1 P reads
        }
    }

    // ---- epilogue: scale by dist/l, store ----
    float dist = g_dist[b * A_ + js];
    float sc0 = dist / l0, sc1 = dist / l1;
    int r0 = qt * 128 + wm + g, r1 = r0 + 8;
    float* z0 = g_O + ((size_t)(b * S_ + r0)) * (A_ * DA_) + js * 64;
    float* z1 = g_O + ((size_t)(b * S_ + r1)) * (A_ * DA_) + js * 64;
    #pragma unroll
    for (int ni = 0; ni < 8; ni++) {
        int c = ni * 8 + 2 * q;
        float2 v0; v0.x = Ofr[ni][0] * sc0; v0.y = Ofr[ni][1] * sc0;
        float2 v1; v1.x = Ofr[ni][2] * sc1; v1.y = Ofr[ni][3] * sc1;
        *(float2*)&z0[c] = v0;
        *(float2*)&z1[c] = v1;
    }
}

// ---------------- kernel 5: Z = O_final @ Wo + bo (tf32 tensor cores) ----------------
__global__ __launch_bounds__(256) void out_gemm_tf32(
    const float* __restrict__ Wo, const float* __restrict__ bo,
    float* __restrict__ Z)
{
    int m0 = blockIdx.y * 128;
    int n0 = blockIdx.x * 128;

    __shared__ float As[2][128][20];
    __shared__ float Bs[2][16][136];

    int tid  = threadIdx.x;
    int wid  = tid >> 5;
    int lane = tid & 31;
    int g    = lane >> 2, q = lane & 3;
    int wm   = (wid >> 2) * 64;
    int wn   = (wid & 3) * 32;

    float acc[4][4][4];
    #pragma unroll
    for (int mi = 0; mi < 4; mi++)
        #pragma unroll
        for (int ni = 0; ni < 4; ni++)
            #pragma unroll
            for (int c = 0; c < 4; c++) acc[mi][ni][c] = 0.f;

    float4 ra[2], rb[2];

    auto ldg_tile = [&](int k0) {
        #pragma unroll
        for (int i = 0; i < 2; i++) {
            int f   = tid + i * 256;
            int row = f >> 2, kc = (f & 3) * 4;
            ra[i] = *(const float4*)(g_O + (size_t)(m0 + row) * (A_ * DA_) + k0 + kc);
        }
        #pragma unroll
        for (int i = 0; i < 2; i++) {
            int f  = tid + i * 256;
            int kk = f >> 5, nn = (f & 31) * 4;
            rb[i] = *(const float4*)(Wo + (size_t)(k0 + kk) * D_ + n0 + nn);
        }
    };
    auto sts_tile = [&](int buf) {
        #pragma unroll
        for (int i = 0; i < 2; i++) {
            int f   = tid + i * 256;
            int row = f >> 2, kc = (f & 3) * 4;
            As[buf][row][kc + 0] = f2tf32(ra[i].x);
            As[buf][row][kc + 1] = f2tf32(ra[i].y);
            As[buf][row][kc + 2] = f2tf32(ra[i].z);
            As[buf][row][kc + 3] = f2tf32(ra[i].w);
        }
        #pragma unroll
        for (int i = 0; i < 2; i++) {
            int f  = tid + i * 256;
            int kk = f >> 5, nn = (f & 31) * 4;
            Bs[buf][kk][nn + 0] = f2tf32(rb[i].x);
            Bs[buf][kk][nn + 1] = f2tf32(rb[i].y);
            Bs[buf][kk][nn + 2] = f2tf32(rb[i].z);
            Bs[buf][kk][nn + 3] = f2tf32(rb[i].w);
        }
    };
    auto compute = [&](int buf) {
        #pragma unroll
        for (int kk = 0; kk < 16; kk += 8) {
            uint32_t afr[4][4], bfr[4][2];
            #pragma unroll
            for (int mi = 0; mi < 4; mi++) {
                int m = wm + mi * 16 + g;
                afr[mi][0] = __float_as_uint(As[buf][m    ][kk + q    ]);
                afr[mi][1] = __float_as_uint(As[buf][m + 8][kk + q    ]);
                afr[mi][2] = __float_as_uint(As[buf][m    ][kk + q + 4]);
                afr[mi][3] = __float_as_uint(As[buf][m + 8][kk + q + 4]);
            }
            #pragma unroll
            for (int ni = 0; ni < 4; ni++) {
                int n = wn + ni * 8 + g;
                bfr[ni][0] = __float_as_uint(Bs[buf][kk + q    ][n]);
                bfr[ni][1] = __float_as_uint(Bs[buf][kk + q + 4][n]);
            }
            #pragma unroll
            for (int mi = 0; mi < 4; mi++)
                #pragma unroll
                for (int ni = 0; ni < 4; ni++)
                    mma_tf32(acc[mi][ni], afr[mi][0], afr[mi][1], afr[mi][2], afr[mi][3],
                             bfr[ni][0], bfr[ni][1]);
        }
    };

    ldg_tile(0);
    sts_tile(0);
    __syncthreads();
    int buf = 0;
    for (int k0 = 16; k0 <= A_ * DA_; k0 += 16) {
        bool has = (k0 < A_ * DA_);
        if (has) ldg_tile(k0);
        compute(buf);
        if (has) sts_tile(buf ^ 1);
        __syncthreads();
        buf ^= 1;
    }

    #pragma unroll
    for (int mi = 0; mi < 4; mi++) {
        int m = m0 + wm + mi * 16 + g;
        #pragma unroll
        for (int ni = 0; ni < 4; ni++) {
            int n = n0 + wn + ni * 8 + q * 2;
            float b0v = bo[n], b1v = bo[n + 1];
            Z[(size_t)m * D_ + n]           = acc[mi][ni][0] + b0v;
            Z[(size_t)m * D_ + n + 1]       = acc[mi][ni][1] + b1v;
            Z[(size_t)(m + 8) * D_ + n]     = acc[mi][ni][2] + b0v;
            Z[(size_t)(m + 8) * D_ + n + 1] = acc[mi][ni][3] + b1v;
        }
    }
}

// ---------------- launch ----------------
extern "C" void kernel_launch(void* const* d_in, const int* in_sizes, int n_in,
                              void* d_out, int out_size) {
    const float* x     = (const float*)d_in[0];
    const float* Wq    = (const float*)d_in[1];
    const float* bq    = (const float*)d_in[2];
    const float* Wk    = (const float*)d_in[3];
    const float* bk    = (const float*)d_in[4];
    const float* Wv    = (const float*)d_in[5];
    const float* bv    = (const float*)d_in[6];
    const float* Wr    = (const float*)d_in[7];
    const float* br    = (const float*)d_in[8];
    const float* gamma = (const float*)d_in[9];
    const float* beta  = (const float*)d_in[10];
    const float* Wo    = (const float*)d_in[11];
    const float* bo    = (const float*)d_in[12];
    float* Z = (float*)d_out;

    cudaFuncSetAttribute(attn_tc_kernel, cudaFuncAttributeMaxDynamicSharedMemorySize,
                         ATTN_TC_SMEM_FLOATS * (int)sizeof(float));

    zero_xbar_kernel<<<B_, 1024>>>();
    mean_kernel<<<dim3(32, B_), 1024>>>(x);
    router_kernel<<<B_, 512>>>(Wr, br, gamma, beta);
    qkv_gemm_tf32<<<dim3(6, 16, B_), 256>>>(x, Wq, bq, Wk, bk, Wv, bv);
    attn_tc_kernel<<<dim3(16, 32), 256, ATTN_TC_SMEM_FLOATS * (int)sizeof(float)>>>();
    out_gemm_tf32<<<dim3(8, 128), 256>>>(Wo, bo, Z);
}

// round 13
// speedup vs baseline: 3.0266x; 1.0295x over previous
#include <cuda_runtime.h>
#include <math.h>
#include <stdint.h>

#define B_  8
#define S_  2048
#define D_  1024
#define H_  16
#define A_  4
#define DA_ 64

// ---------------- scratch (static device memory; no allocation) ----------------
__device__ float g_xbar[B_ * D_];
__device__ float g_dist[B_ * A_];
__device__ int   g_idx [B_ * A_];
__device__ float g_Q[(size_t)B_ * A_ * S_ * DA_];   // (b*4+j, s, d)
__device__ float g_K[(size_t)B_ * A_ * S_ * DA_];
__device__ float g_V[(size_t)B_ * A_ * S_ * DA_];
__device__ float g_O[(size_t)B_ * S_ * A_ * DA_];   // (b*S+s, j*64+d)

// ---------------- helpers ----------------
__device__ __forceinline__ float f2tf32(float x) {
    asm("cvt.rna.tf32.f32 %0, %0;" : "+f"(x));
    return x;
}

__device__ __forceinline__ void mma_tf32(float* c,
    uint32_t a0, uint32_t a1, uint32_t a2, uint32_t a3,
    uint32_t b0, uint32_t b1)
{
    asm volatile(
        "mma.sync.aligned.m16n8k8.row.col.f32.tf32.tf32.f32 "
        "{%0,%1,%2,%3}, {%4,%5,%6,%7}, {%8,%9}, {%0,%1,%2,%3};"
        : "+f"(c[0]), "+f"(c[1]), "+f"(c[2]), "+f"(c[3])
        : "r"(a0), "r"(a1), "r"(a2), "r"(a3), "r"(b0), "r"(b1));
}

// ---------------- kernel 0: zero xbar ----------------
__global__ void zero_xbar_kernel() {
    g_xbar[blockIdx.x * 1024 + threadIdx.x] = 0.0f;
}

// ---------------- kernel 1: xbar = mean_S x ----------------
__global__ void mean_kernel(const float* __restrict__ x) {
    int b  = blockIdx.y;
    int d  = threadIdx.x;
    int s0 = blockIdx.x * 64;
    const float* xp = x + ((size_t)b * S_ + s0) * D_ + d;
    float acc = 0.0f;
    #pragma unroll 8
    for (int s = 0; s < 64; s++) acc += xp[(size_t)s * D_];
    atomicAdd(&g_xbar[b * D_ + d], acc * (1.0f / (float)S_));
}

// ---------------- kernel 2: router ----------------
__global__ void router_kernel(const float* __restrict__ Wr, const float* __restrict__ br,
                              const float* __restrict__ gamma, const float* __restrict__ beta) {
    int b = blockIdx.x;
    int w = threadIdx.x >> 5;
    int lane = threadIdx.x & 31;
    __shared__ float r_s[H_];
    const float* xb = g_xbar + b * D_;
    float acc = 0.0f;
    for (int d = lane; d < D_; d += 32)
        acc += xb[d] * Wr[d * H_ + w];
    #pragma unroll
    for (int off = 16; off; off >>= 1) acc += __shfl_xor_sync(0xffffffffu, acc, off);
    if (lane == 0) r_s[w] = acc + br[w];
    __syncthreads();
    if (threadIdx.x == 0) {
        float r[H_];
        for (int h = 0; h < H_; h++) r[h] = r_s[h];
        float mu = 0.f;
        for (int h = 0; h < H_; h++) mu += r[h];
        mu *= (1.0f / H_);
        float var = 0.f;
        for (int h = 0; h < H_; h++) { float dd = r[h] - mu; var += dd * dd; }
        var *= (1.0f / H_);
        float inv = rsqrtf(var + 1e-5f);
        float rn[H_];
        for (int h = 0; h < H_; h++) rn[h] = (r[h] - mu) * inv * gamma[h] + beta[h];
        float mx = rn[0];
        for (int h = 1; h < H_; h++) mx = fmaxf(mx, rn[h]);
        float e[H_]; float ssum = 0.f;
        for (int h = 0; h < H_; h++) { e[h] = expf(rn[h] - mx); ssum += e[h]; }
        float isum = 1.0f / ssum;
        for (int h = 0; h < H_; h++) e[h] *= isum;
        float tmp[H_];
        for (int h = 0; h < H_; h++) tmp[h] = e[h];
        int idx[A_];
        for (int j = 0; j < A_; j++) {
            int bi = 0; float bv = tmp[0];
            for (int h = 1; h < H_; h++) if (tmp[h] > bv) { bv = tmp[h]; bi = h; }
            idx[j] = bi; tmp[bi] = -1e30f;
        }
        for (int i = 0; i < A_; i++)
            for (int j = i + 1; j < A_; j++)
                if (idx[j] < idx[i]) { int t = idx[i]; idx[i] = idx[j]; idx[j] = t; }
        for (int j = 0; j < A_; j++) {
            g_idx [b * A_ + j] = idx[j];
            g_dist[b * A_ + j] = e[idx[j]];
        }
    }
}

// ---------------- kernel 3: gathered QKV projection (tf32, KB=32 k-tile) ----------------
// Dynamic smem: As [2][128][36] + Bs [2][32][136] = 17920 floats = 71680 B -> 2 blocks/SM.
// KB=32 halves barrier count vs KB=16 and doubles MMA work per sync window.
#define QKV_AS_STRIDE 36
#define QKV_BS_STRIDE 136
#define QKV_AS_SIZE   (128 * QKV_AS_STRIDE)         // 4608 floats per buffer
#define QKV_BS_SIZE   (32 * QKV_BS_STRIDE)          // 4352 floats per buffer
#define QKV_SMEM_FLOATS (2 * QKV_AS_SIZE + 2 * QKV_BS_SIZE)   // 17920 floats = 71680 B

__global__ __launch_bounds__(256, 2) void qkv_gemm_tf32(
    const float* __restrict__ x,
    const float* __restrict__ Wq, const float* __restrict__ bq,
    const float* __restrict__ Wk, const float* __restrict__ bk,
    const float* __restrict__ Wv, const float* __restrict__ bv)
{
    extern __shared__ float qsm[];

    int b     = blockIdx.z;
    int mt    = blockIdx.y;
    int which = blockIdx.x >> 1;
    int n0    = (blockIdx.x & 1) * 128;

    const float* W    = which == 0 ? Wq : (which == 1 ? Wk : Wv);
    const float* bias = which == 0 ? bq : (which == 1 ? bk : bv);
    float*       Out  = which == 0 ? g_Q : (which == 1 ? g_K : g_V);

    int tid  = threadIdx.x;
    int wid  = tid >> 5;
    int lane = tid & 31;
    int g    = lane >> 2, q = lane & 3;
    int wm   = (wid >> 2) * 64;
    int wn   = (wid & 3) * 32;

    int hc[2];
    hc[0] = g_idx[b * A_ + (n0 >> 6)    ] * 64;
    hc[1] = g_idx[b * A_ + (n0 >> 6) + 1] * 64;

    const float* xb = x + ((size_t)b * S_ + (size_t)mt * 128) * D_;

    float acc[4][4][4];
    #pragma unroll
    for (int mi = 0; mi < 4; mi++)
        #pragma unroll
        for (int ni = 0; ni < 4; ni++)
            #pragma unroll
            for (int c = 0; c < 4; c++) acc[mi][ni][c] = 0.f;

    float4 ra[4], rb[4];

    // A tile: 128 rows x 32 k = 1024 float4; thread f -> row=f>>3, kc=(f&7)*4
    // B tile: 32 k x 128 n   = 1024 float4; thread f -> kk=f>>5, nn=(f&31)*4
    auto ldg_tile = [&](int k0) {
        #pragma unroll
        for (int i = 0; i < 4; i++) {
            int f   = tid + i * 256;
            int row = f >> 3, kc = (f & 7) * 4;
            ra[i] = *(const float4*)(xb + (size_t)row * D_ + k0 + kc);
        }
        #pragma unroll
        for (int i = 0; i < 4; i++) {
            int f   = tid + i * 256;
            int kk  = f >> 5, nn = (f & 31) * 4;
            int col = hc[nn >> 6] + (nn & 63);
            rb[i] = *(const float4*)(W + (size_t)(k0 + kk) * (H_ * DA_) + col);
        }
    };
    auto sts_tile = [&](int buf) {
        float* As = qsm + buf * QKV_AS_SIZE;
        float* Bs = qsm + 2 * QKV_AS_SIZE + buf * QKV_BS_SIZE;
        #pragma unroll
        for (int i = 0; i < 4; i++) {
            int f   = tid + i * 256;
            int row = f >> 3, kc = (f & 7) * 4;
            float* p = As + row * QKV_AS_STRIDE + kc;
            p[0] = f2tf32(ra[i].x);
            p[1] = f2tf32(ra[i].y);
            p[2] = f2tf32(ra[i].z);
            p[3] = f2tf32(ra[i].w);
        }
        #pragma unroll
        for (int i = 0; i < 4; i++) {
            int f  = tid + i * 256;
            int kk = f >> 5, nn = (f & 31) * 4;
            float* p = Bs + kk * QKV_BS_STRIDE + nn;
            p[0] = f2tf32(rb[i].x);
            p[1] = f2tf32(rb[i].y);
            p[2] = f2tf32(rb[i].z);
            p[3] = f2tf32(rb[i].w);
        }
    };
    auto compute = [&](int buf) {
        float* As = qsm + buf * QKV_AS_SIZE;
        float* Bs = qsm + 2 * QKV_AS_SIZE + buf * QKV_BS_SIZE;
        #pragma unroll
        for (int kk = 0; kk < 32; kk += 8) {
            uint32_t afr[4][4], bfr[4][2];
            #pragma unroll
            for (int mi = 0; mi < 4; mi++) {
                int m = wm + mi * 16 + g;
                afr[mi][0] = __float_as_uint(As[(m    ) * QKV_AS_STRIDE + kk + q    ]);
                afr[mi][1] = __float_as_uint(As[(m + 8) * QKV_AS_STRIDE + kk + q    ]);
                afr[mi][2] = __float_as_uint(As[(m    ) * QKV_AS_STRIDE + kk + q + 4]);
                afr[mi][3] = __float_as_uint(As[(m + 8) * QKV_AS_STRIDE + kk + q + 4]);
            }
            #pragma unroll
            for (int ni = 0; ni < 4; ni++) {
                int n = wn + ni * 8 + g;
                bfr[ni][0] = __float_as_uint(Bs[(kk + q    ) * QKV_BS_STRIDE + n]);
                bfr[ni][1] = __float_as_uint(Bs[(kk + q + 4) * QKV_BS_STRIDE + n]);
            }
            #pragma unroll
            for (int mi = 0; mi < 4; mi++)
                #pragma unroll
                for (int ni = 0; ni < 4; ni++)
                    mma_tf32(acc[mi][ni], afr[mi][0], afr[mi][1], afr[mi][2], afr[mi][3],
                             bfr[ni][0], bfr[ni][1]);
        }
    };

    ldg_tile(0);
    sts_tile(0);
    __syncthreads();
    int buf = 0;
    for (int k0 = 32; k0 <= D_; k0 += 32) {
        bool has = (k0 < D_);
        if (has) ldg_tile(k0);
        compute(buf);
        if (has) sts_tile(buf ^ 1);
        __syncthreads();
        buf ^= 1;
    }

    #pragma unroll
    for (int mi = 0; mi < 4; mi++) {
        int m = mt * 128 + wm + mi * 16 + g;
        #pragma unroll
        for (int ni = 0; ni < 4; ni++) {
            int nn = wn + ni * 8 + q * 2;
            int hs = nn >> 6, d = nn & 63;
            int headslot = (n0 >> 6) + hs;
            float bz0 = bias[hc[hs] + d];
            float bz1 = bias[hc[hs] + d + 1];
            float* outp = Out + (((size_t)(b * A_ + headslot)) * S_) * DA_ + d;
            outp[(size_t)m * DA_ + 0]       = acc[mi][ni][0] + bz0;
            outp[(size_t)m * DA_ + 1]       = acc[mi][ni][1] + bz1;
            outp[(size_t)(m + 8) * DA_ + 0] = acc[mi][ni][2] + bz0;
            outp[(size_t)(m + 8) * DA_ + 1] = acc[mi][ni][3] + bz1;
        }
    }
}

// ---------------- kernel 4: flash attention on tf32 tensor cores ----------------
// grid (16 q-tiles of 128 rows, 32 (b,head) pairs), block 256 (8 warps).
// PV phase-split; P (128x68) aliases Ks. smem 104KB -> 2 blocks/SM.
#define QS_STRIDE 68
#define KS_STRIDE 68
#define VS_STRIDE 72
#define QS_OFF    0
#define KS_OFF    (128 * QS_STRIDE)                // 8704
#define VS_OFF    (KS_OFF + 128 * KS_STRIDE)       // 17408
#define ATTN_TC_SMEM_FLOATS (VS_OFF + 128 * VS_STRIDE)   // 26624 floats = 106496 B

__global__ __launch_bounds__(256) void attn_tc_kernel() {
    extern __shared__ float sm[];
    float* Qs = sm + QS_OFF;
    float* Ks = sm + KS_OFF;
    float* Ps = sm + KS_OFF;        // alias: P overwrites K tile after QK^T
    float* Vs = sm + VS_OFF;

    int qt  = blockIdx.x;
    int bj  = blockIdx.y;
    int b   = bj >> 2, js = bj & 3;
    int tid = threadIdx.x;
    int wid  = tid >> 5;
    int lane = tid & 31;
    int g = lane >> 2, q = lane & 3;
    int wm = wid * 16;                    // warp's 16-row strip in the 128-row q-tile
    unsigned qmask = 0xffffffffu;

    const float* Qg = g_Q + (size_t)bj * S_ * DA_ + (size_t)qt * 128 * DA_;
    const float* Kg = g_K + (size_t)bj * S_ * DA_;
    const float* Vg = g_V + (size_t)bj * S_ * DA_;

    // ---- load Q tile (128 x 64) ----
    #pragma unroll
    for (int i = 0; i < 8; i++) {
        int f = tid + i * 256;
        int r = f >> 4, c = (f & 15) * 4;
        float4 v = ((const float4*)Qg)[f];
        Qs[r * QS_STRIDE + c + 0] = f2tf32(v.x);
        Qs[r * QS_STRIDE + c + 1] = f2tf32(v.y);
        Qs[r * QS_STRIDE + c + 2] = f2tf32(v.z);
        Qs[r * QS_STRIDE + c + 3] = f2tf32(v.w);
    }

    float Sfr[16][4];
    float Ofr[8][4];
    #pragma unroll
    for (int i = 0; i < 8; i++)
        #pragma unroll
        for (int c = 0; c < 4; c++) Ofr[i][c] = 0.f;
    float m0 = -1e30f, m1 = -1e30f, l0 = 0.f, l1 = 0.f;

    for (int t = 0; t < 16; t++) {
        __syncthreads();   // prev iter PV done reading Ps/Vs; Q fill covered on t=0
        // ---- fill K,V tiles (128 x 64 each) ----
        const float4* Kt = (const float4*)(Kg + (size_t)t * 128 * DA_);
        const float4* Vt = (const float4*)(Vg + (size_t)t * 128 * DA_);
        #pragma unroll
        for (int i = 0; i < 8; i++) {
            int f = tid + i * 256;
            int r = f >> 4, c = (f & 15) * 4;
            float4 kv = Kt[f];
            Ks[r * KS_STRIDE + c + 0] = f2tf32(kv.x);
            Ks[r * KS_STRIDE + c + 1] = f2tf32(kv.y);
            Ks[r * KS_STRIDE + c + 2] = f2tf32(kv.z);
            Ks[r * KS_STRIDE + c + 3] = f2tf32(kv.w);
            float4 vv = Vt[f];
            Vs[r * VS_STRIDE + c + 0] = f2tf32(vv.x);
            Vs[r * VS_STRIDE + c + 1] = f2tf32(vv.y);
            Vs[r * VS_STRIDE + c + 2] = f2tf32(vv.z);
            Vs[r * VS_STRIDE + c + 3] = f2tf32(vv.w);
        }
        __syncthreads();

        // ---- S = Q @ K^T  (warp: 16 rows x 128 cols) ----
        #pragma unroll
        for (int ni = 0; ni < 16; ni++)
            #pragma unroll
            for (int c = 0; c < 4; c++) Sfr[ni][c] = 0.f;

        #pragma unroll
        for (int ks = 0; ks < 8; ks++) {
            int kk = ks * 8;
            uint32_t a0 = __float_as_uint(Qs[(wm + g    ) * QS_STRIDE + kk + q    ]);
            uint32_t a1 = __float_as_uint(Qs[(wm + g + 8) * QS_STRIDE + kk + q    ]);
            uint32_t a2 = __float_as_uint(Qs[(wm + g    ) * QS_STRIDE + kk + q + 4]);
            uint32_t a3 = __float_as_uint(Qs[(wm + g + 8) * QS_STRIDE + kk + q + 4]);
            #pragma unroll
            for (int ni = 0; ni < 16; ni++) {
                int n = ni * 8 + g;
                uint32_t b0 = __float_as_uint(Ks[n * KS_STRIDE + kk + q    ]);
                uint32_t b1 = __float_as_uint(Ks[n * KS_STRIDE + kk + q + 4]);
                mma_tf32(Sfr[ni], a0, a1, a2, a3, b0, b1);
            }
        }

        // ---- online softmax (rows wm+g, wm+g+8; quad reduce over q) ----
        float mx0 = -1e30f, mx1 = -1e30f;
        #pragma unroll
        for (int ni = 0; ni < 16; ni++) {
            mx0 = fmaxf(mx0, fmaxf(Sfr[ni][0], Sfr[ni][1]));
            mx1 = fmaxf(mx1, fmaxf(Sfr[ni][2], Sfr[ni][3]));
        }
        mx0 = fmaxf(mx0, __shfl_xor_sync(qmask, mx0, 1));
        mx0 = fmaxf(mx0, __shfl_xor_sync(qmask, mx0, 2));
        mx1 = fmaxf(mx1, __shfl_xor_sync(qmask, mx1, 1));
        mx1 = fmaxf(mx1, __shfl_xor_sync(qmask, mx1, 2));
        mx0 *= 0.125f; mx1 *= 0.125f;   // scale applied after max (monotone)
        float mn0 = fmaxf(m0, mx0), mn1 = fmaxf(m1, mx1);
        float cr0 = __expf(m0 - mn0), cr1 = __expf(m1 - mn1);
        float ts0 = 0.f, ts1 = 0.f;
        #pragma unroll
        for (int ni = 0; ni < 16; ni++) {
            float p0 = __expf(Sfr[ni][0] * 0.125f - mn0);
            float p1 = __expf(Sfr[ni][1] * 0.125f - mn0);
            float p2 = __expf(Sfr[ni][2] * 0.125f - mn1);
            float p3 = __expf(Sfr[ni][3] * 0.125f - mn1);
            Sfr[ni][0] = p0; Sfr[ni][1] = p1; Sfr[ni][2] = p2; Sfr[ni][3] = p3;
            ts0 += p0 + p1; ts1 += p2 + p3;
        }
        ts0 += __shfl_xor_sync(qmask, ts0, 1);
        ts0 += __shfl_xor_sync(qmask, ts0, 2);
        ts1 += __shfl_xor_sync(qmask, ts1, 1);
        ts1 += __shfl_xor_sync(qmask, ts1, 2);
        l0 = l0 * cr0 + ts0;  m0 = mn0;
        l1 = l1 * cr1 + ts1;  m1 = mn1;
        #pragma unroll
        for (int i = 0; i < 8; i++) {
            Ofr[i][0] *= cr0; Ofr[i][1] *= cr0;
            Ofr[i][2] *= cr1; Ofr[i][3] *= cr1;
        }

        __syncthreads();   // all warps done reading Ks before P overwrites it

        // ---- PV in two phases; P buffer holds 64 k-cols at a time ----
        #pragma unroll
        for (int ph = 0; ph < 2; ph++) {
            // write P cols [ph*64, ph*64+64) into Ps (stride 68), warp-private rows
            #pragma unroll
            for (int ni = 0; ni < 8; ni++) {
                int nig = ph * 8 + ni;
                float2 p01; p01.x = f2tf32(Sfr[nig][0]); p01.y = f2tf32(Sfr[nig][1]);
                float2 p23; p23.x = f2tf32(Sfr[nig][2]); p23.y = f2tf32(Sfr[nig][3]);
                *(float2*)&Ps[(wm + g    ) * KS_STRIDE + ni * 8 + 2 * q] = p01;
                *(float2*)&Ps[(wm + g + 8) * KS_STRIDE + ni * 8 + 2 * q] = p23;
            }
            __syncwarp();   // warp reads back only its own 16 rows

            // O += P_phase @ V_phase  (V rows ph*64 .. ph*64+63)
            #pragma unroll
            for (int ks = 0; ks < 8; ks++) {
                int kk = ks * 8;
                uint32_t a0 = __float_as_uint(Ps[(wm + g    ) * KS_STRIDE + kk + q    ]);
                uint32_t a1 = __float_as_uint(Ps[(wm + g + 8) * KS_STRIDE + kk + q    ]);
                uint32_t a2 = __float_as_uint(Ps[(wm + g    ) * KS_STRIDE + kk + q + 4]);
                uint32_t a3 = __float_as_uint(Ps[(wm + g + 8) * KS_STRIDE + kk + q + 4]);
                int vr = ph * 64 + kk;
                #pragma unroll
                for (int ni = 0; ni < 8; ni++) {
                    int n = ni * 8 + g;
                    uint32_t b0 = __float_as_uint(Vs[(vr + q    ) * VS_STRIDE + n]);
                    uint32_t b1 = __float_as_uint(Vs[(vr + q + 4) * VS_STRIDE + n]);
                    mma_tf32(Ofr[ni], a0, a1, a2, a3, b0, b1);
                }
            }
            __syncwarp();   // phase-2 P write must not race phase-1 P reads
        }
    }

    // ---- epilogue: scale by dist/l, store ----
    float dist = g_dist[b * A_ + js];
    float sc0 = dist / l0, sc1 = dist / l1;
    int r0 = qt * 128 + wm + g, r1 = r0 + 8;
    float* z0 = g_O + ((size_t)(b * S_ + r0)) * (A_ * DA_) + js * 64;
    float* z1 = g_O + ((size_t)(b * S_ + r1)) * (A_ * DA_) + js * 64;
    #pragma unroll
    for (int ni = 0; ni < 8; ni++) {
        int c = ni * 8 + 2 * q;
        float2 v0; v0.x = Ofr[ni][0] * sc0; v0.y = Ofr[ni][1] * sc0;
        float2 v1; v1.x = Ofr[ni][2] * sc1; v1.y = Ofr[ni][3] * sc1;
        *(float2*)&z0[c] = v0;
        *(float2*)&z1[c] = v1;
    }
}

// ---------------- kernel 5: Z = O_final @ Wo + bo (tf32 tensor cores) ----------------
__global__ __launch_bounds__(256) void out_gemm_tf32(
    const float* __restrict__ Wo, const float* __restrict__ bo,
    float* __restrict__ Z)
{
    int m0 = blockIdx.y * 128;
    int n0 = blockIdx.x * 128;

    __shared__ float As[2][128][20];
    __shared__ float Bs[2][16][136];

    int tid  = threadIdx.x;
    int wid  = tid >> 5;
    int lane = tid & 31;
    int g    = lane >> 2, q = lane & 3;
    int wm   = (wid >> 2) * 64;
    int wn   = (wid & 3) * 32;

    float acc[4][4][4];
    #pragma unroll
    for (int mi = 0; mi < 4; mi++)
        #pragma unroll
        for (int ni = 0; ni < 4; ni++)
            #pragma unroll
            for (int c = 0; c < 4; c++) acc[mi][ni][c] = 0.f;

    float4 ra[2], rb[2];

    auto ldg_tile = [&](int k0) {
        #pragma unroll
        for (int i = 0; i < 2; i++) {
            int f   = tid + i * 256;
            int row = f >> 2, kc = (f & 3) * 4;
            ra[i] = *(const float4*)(g_O + (size_t)(m0 + row) * (A_ * DA_) + k0 + kc);
        }
        #pragma unroll
        for (int i = 0; i < 2; i++) {
            int f  = tid + i * 256;
            int kk = f >> 5, nn = (f & 31) * 4;
            rb[i] = *(const float4*)(Wo + (size_t)(k0 + kk) * D_ + n0 + nn);
        }
    };
    auto sts_tile = [&](int buf) {
        #pragma unroll
        for (int i = 0; i < 2; i++) {
            int f   = tid + i * 256;
            int row = f >> 2, kc = (f & 3) * 4;
            As[buf][row][kc + 0] = f2tf32(ra[i].x);
            As[buf][row][kc + 1] = f2tf32(ra[i].y);
            As[buf][row][kc + 2] = f2tf32(ra[i].z);
            As[buf][row][kc + 3] = f2tf32(ra[i].w);
        }
        #pragma unroll
        for (int i = 0; i < 2; i++) {
            int f  = tid + i * 256;
            int kk = f >> 5, nn = (f & 31) * 4;
            Bs[buf][kk][nn + 0] = f2tf32(rb[i].x);
            Bs[buf][kk][nn + 1] = f2tf32(rb[i].y);
            Bs[buf][kk][nn + 2] = f2tf32(rb[i].z);
            Bs[buf][kk][nn + 3] = f2tf32(rb[i].w);
        }
    };
    auto compute = [&](int buf) {
        #pragma unroll
        for (int kk = 0; kk < 16; kk += 8) {
            uint32_t afr[4][4], bfr[4][2];
            #pragma unroll
            for (int mi = 0; mi < 4; mi++) {
                int m = wm + mi * 16 + g;
                afr[mi][0] = __float_as_uint(As[buf][m    ][kk + q    ]);
                afr[mi][1] = __float_as_uint(As[buf][m + 8][kk + q    ]);
                afr[mi][2] = __float_as_uint(As[buf][m    ][kk + q + 4]);
                afr[mi][3] = __float_as_uint(As[buf][m + 8][kk + q + 4]);
            }
            #pragma unroll
            for (int ni = 0; ni < 4; ni++) {
                int n = wn + ni * 8 + g;
                bfr[ni][0] = __float_as_uint(Bs[buf][kk + q    ][n]);
                bfr[ni][1] = __float_as_uint(Bs[buf][kk + q + 4][n]);
            }
            #pragma unroll
            for (int mi = 0; mi < 4; mi++)
                #pragma unroll
                for (int ni = 0; ni < 4; ni++)
                    mma_tf32(acc[mi][ni], afr[mi][0], afr[mi][1], afr[mi][2], afr[mi][3],
                             bfr[ni][0], bfr[ni][1]);
        }
    };

    ldg_tile(0);
    sts_tile(0);
    __syncthreads();
    int buf = 0;
    for (int k0 = 16; k0 <= A_ * DA_; k0 += 16) {
        bool has = (k0 < A_ * DA_);
        if (has) ldg_tile(k0);
        compute(buf);
        if (has) sts_tile(buf ^ 1);
        __syncthreads();
        buf ^= 1;
    }

    #pragma unroll
    for (int mi = 0; mi < 4; mi++) {
        int m = m0 + wm + mi * 16 + g;
        #pragma unroll
        for (int ni = 0; ni < 4; ni++) {
            int n = n0 + wn + ni * 8 + q * 2;
            float b0v = bo[n], b1v = bo[n + 1];
            Z[(size_t)m * D_ + n]           = acc[mi][ni][0] + b0v;
            Z[(size_t)m * D_ + n + 1]       = acc[mi][ni][1] + b1v;
            Z[(size_t)(m + 8) * D_ + n]     = acc[mi][ni][2] + b0v;
            Z[(size_t)(m + 8) * D_ + n + 1] = acc[mi][ni][3] + b1v;
        }
    }
}

// ---------------- launch ----------------
extern "C" void kernel_launch(void* const* d_in, const int* in_sizes, int n_in,
                              void* d_out, int out_size) {
    const float* x     = (const float*)d_in[0];
    const float* Wq    = (const float*)d_in[1];
    const float* bq    = (const float*)d_in[2];
    const float* Wk    = (const float*)d_in[3];
    const float* bk    = (const float*)d_in[4];
    const float* Wv    = (const float*)d_in[5];
    const float* bv    = (const float*)d_in[6];
    const float* Wr    = (const float*)d_in[7];
    const float* br    = (const float*)d_in[8];
    const float* gamma = (const float*)d_in[9];
    const float* beta  = (const float*)d_in[10];
    const float* Wo    = (const float*)d_in[11];
    const float* bo    = (const float*)d_in[12];
    float* Z = (float*)d_out;

    cudaFuncSetAttribute(attn_tc_kernel, cudaFuncAttributeMaxDynamicSharedMemorySize,
                         ATTN_TC_SMEM_FLOATS * (int)sizeof(float));
    cudaFuncSetAttribute(qkv_gemm_tf32, cudaFuncAttributeMaxDynamicSharedMemorySize,
                         QKV_SMEM_FLOATS * (int)sizeof(float));

    zero_xbar_kernel<<<B_, 1024>>>();
    mean_kernel<<<dim3(32, B_), 1024>>>(x);
    router_kernel<<<B_, 512>>>(Wr, br, gamma, beta);
    qkv_gemm_tf32<<<dim3(6, 16, B_), 256, QKV_SMEM_FLOATS * (int)sizeof(float)>>>(
        x, Wq, bq, Wk, bk, Wv, bv);
    attn_tc_kernel<<<dim3(16, 32), 256, ATTN_TC_SMEM_FLOATS * (int)sizeof(float)>>>();
    out_gemm_tf32<<<dim3(8, 128), 256>>>(Wo, bo, Z);
}

// round 15
// speedup vs baseline: 3.0362x; 1.0031x over previous
#include <cuda_runtime.h>
#include <math.h>
#include <stdint.h>

#define B_  8
#define S_  2048
#define D_  1024
#define H_  16
#define A_  4
#define DA_ 64

// ---------------- scratch (static device memory; no allocation) ----------------
__device__ float g_xbar[B_ * D_];
__device__ float g_dist[B_ * A_];
__device__ int   g_idx [B_ * A_];
__device__ float g_Q[(size_t)B_ * A_ * S_ * DA_];   // (b*4+j, s, d)
__device__ float g_K[(size_t)B_ * A_ * S_ * DA_];
__device__ float g_V[(size_t)B_ * A_ * S_ * DA_];
__device__ float g_O[(size_t)B_ * S_ * A_ * DA_];   // (b*S+s, j*64+d)

// ---------------- helpers ----------------
__device__ __forceinline__ float f2tf32(float x) {
    asm("cvt.rna.tf32.f32 %0, %0;" : "+f"(x));
    return x;
}

__device__ __forceinline__ void mma_tf32(float* c,
    uint32_t a0, uint32_t a1, uint32_t a2, uint32_t a3,
    uint32_t b0, uint32_t b1)
{
    asm volatile(
        "mma.sync.aligned.m16n8k8.row.col.f32.tf32.tf32.f32 "
        "{%0,%1,%2,%3}, {%4,%5,%6,%7}, {%8,%9}, {%0,%1,%2,%3};"
        : "+f"(c[0]), "+f"(c[1]), "+f"(c[2]), "+f"(c[3])
        : "r"(a0), "r"(a1), "r"(a2), "r"(a3), "r"(b0), "r"(b1));
}

// ---------------- kernel 0: zero xbar ----------------
__global__ void zero_xbar_kernel() {
    g_xbar[blockIdx.x * 1024 + threadIdx.x] = 0.0f;
}

// ---------------- kernel 1: xbar = mean_S x ----------------
__global__ void mean_kernel(const float* __restrict__ x) {
    int b  = blockIdx.y;
    int d  = threadIdx.x;
    int s0 = blockIdx.x * 64;
    const float* xp = x + ((size_t)b * S_ + s0) * D_ + d;
    float acc = 0.0f;
    #pragma unroll 8
    for (int s = 0; s < 64; s++) acc += xp[(size_t)s * D_];
    atomicAdd(&g_xbar[b * D_ + d], acc * (1.0f / (float)S_));
}

// ---------------- kernel 2: router ----------------
__global__ void router_kernel(const float* __restrict__ Wr, const float* __restrict__ br,
                              const float* __restrict__ gamma, const float* __restrict__ beta) {
    int b = blockIdx.x;
    int w = threadIdx.x >> 5;
    int lane = threadIdx.x & 31;
    __shared__ float r_s[H_];
    const float* xb = g_xbar + b * D_;
    float acc = 0.0f;
    for (int d = lane; d < D_; d += 32)
        acc += xb[d] * Wr[d * H_ + w];
    #pragma unroll
    for (int off = 16; off; off >>= 1) acc += __shfl_xor_sync(0xffffffffu, acc, off);
    if (lane == 0) r_s[w] = acc + br[w];
    __syncthreads();
    if (threadIdx.x == 0) {
        float r[H_];
        for (int h = 0; h < H_; h++) r[h] = r_s[h];
        float mu = 0.f;
        for (int h = 0; h < H_; h++) mu += r[h];
        mu *= (1.0f / H_);
        float var = 0.f;
        for (int h = 0; h < H_; h++) { float dd = r[h] - mu; var += dd * dd; }
        var *= (1.0f / H_);
        float inv = rsqrtf(var + 1e-5f);
        float rn[H_];
        for (int h = 0; h < H_; h++) rn[h] = (r[h] - mu) * inv * gamma[h] + beta[h];
        float mx = rn[0];
        for (int h = 1; h < H_; h++) mx = fmaxf(mx, rn[h]);
        float e[H_]; float ssum = 0.f;
        for (int h = 0; h < H_; h++) { e[h] = expf(rn[h] - mx); ssum += e[h]; }
        float isum = 1.0f / ssum;
        for (int h = 0; h < H_; h++) e[h] *= isum;
        float tmp[H_];
        for (int h = 0; h < H_; h++) tmp[h] = e[h];
        int idx[A_];
        for (int j = 0; j < A_; j++) {
            int bi = 0; float bv = tmp[0];
            for (int h = 1; h < H_; h++) if (tmp[h] > bv) { bv = tmp[h]; bi = h; }
            idx[j] = bi; tmp[bi] = -1e30f;
        }
        for (int i = 0; i < A_; i++)
            for (int j = i + 1; j < A_; j++)
                if (idx[j] < idx[i]) { int t = idx[i]; idx[i] = idx[j]; idx[j] = t; }
        for (int j = 0; j < A_; j++) {
            g_idx [b * A_ + j] = idx[j];
            g_dist[b * A_ + j] = e[idx[j]];
        }
    }
}

// ---------------- kernel 3: gathered QKV projection (tf32, KB=32 k-tile) ----------------
#define QKV_AS_STRIDE 36
#define QKV_BS_STRIDE 136
#define QKV_AS_SIZE   (128 * QKV_AS_STRIDE)
#define QKV_BS_SIZE   (32 * QKV_BS_STRIDE)
#define QKV_SMEM_FLOATS (2 * QKV_AS_SIZE + 2 * QKV_BS_SIZE)   // 17920 floats = 71680 B

__global__ __launch_bounds__(256, 2) void qkv_gemm_tf32(
    const float* __restrict__ x,
    const float* __restrict__ Wq, const float* __restrict__ bq,
    const float* __restrict__ Wk, const float* __restrict__ bk,
    const float* __restrict__ Wv, const float* __restrict__ bv)
{
    extern __shared__ float qsm[];

    int b     = blockIdx.z;
    int mt    = blockIdx.y;
    int which = blockIdx.x >> 1;
    int n0    = (blockIdx.x & 1) * 128;

    const float* W    = which == 0 ? Wq : (which == 1 ? Wk : Wv);
    const float* bias = which == 0 ? bq : (which == 1 ? bk : bv);
    float*       Out  = which == 0 ? g_Q : (which == 1 ? g_K : g_V);

    int tid  = threadIdx.x;
    int wid  = tid >> 5;
    int lane = tid & 31;
    int g    = lane >> 2, q = lane & 3;
    int wm   = (wid >> 2) * 64;
    int wn   = (wid & 3) * 32;

    int hc[2];
    hc[0] = g_idx[b * A_ + (n0 >> 6)    ] * 64;
    hc[1] = g_idx[b * A_ + (n0 >> 6) + 1] * 64;

    const float* xb = x + ((size_t)b * S_ + (size_t)mt * 128) * D_;

    float acc[4][4][4];
    #pragma unroll
    for (int mi = 0; mi < 4; mi++)
        #pragma unroll
        for (int ni = 0; ni < 4; ni++)
            #pragma unroll
            for (int c = 0; c < 4; c++) acc[mi][ni][c] = 0.f;

    float4 ra[4], rb[4];

    auto ldg_tile = [&](int k0) {
        #pragma unroll
        for (int i = 0; i < 4; i++) {
            int f   = tid + i * 256;
            int row = f >> 3, kc = (f & 7) * 4;
            ra[i] = *(const float4*)(xb + (size_t)row * D_ + k0 + kc);
        }
        #pragma unroll
        for (int i = 0; i < 4; i++) {
            int f   = tid + i * 256;
            int kk  = f >> 5, nn = (f & 31) * 4;
            int col = hc[nn >> 6] + (nn & 63);
            rb[i] = *(const float4*)(W + (size_t)(k0 + kk) * (H_ * DA_) + col);
        }
    };
    auto sts_tile = [&](int buf) {
        float* As = qsm + buf * QKV_AS_SIZE;
        float* Bs = qsm + 2 * QKV_AS_SIZE + buf * QKV_BS_SIZE;
        #pragma unroll
        for (int i = 0; i < 4; i++) {
            int f   = tid + i * 256;
            int row = f >> 3, kc = (f & 7) * 4;
            float* p = As + row * QKV_AS_STRIDE + kc;
            p[0] = f2tf32(ra[i].x);
            p[1] = f2tf32(ra[i].y);
            p[2] = f2tf32(ra[i].z);
            p[3] = f2tf32(ra[i].w);
        }
        #pragma unroll
        for (int i = 0; i < 4; i++) {
            int f  = tid + i * 256;
            int kk = f >> 5, nn = (f & 31) * 4;
            float* p = Bs + kk * QKV_BS_STRIDE + nn;
            p[0] = f2tf32(rb[i].x);
            p[1] = f2tf32(rb[i].y);
            p[2] = f2tf32(rb[i].z);
            p[3] = f2tf32(rb[i].w);
        }
    };
    auto compute = [&](int buf) {
        float* As = qsm + buf * QKV_AS_SIZE;
        float* Bs = qsm + 2 * QKV_AS_SIZE + buf * QKV_BS_SIZE;
        #pragma unroll
        for (int kk = 0; kk < 32; kk += 8) {
            uint32_t afr[4][4], bfr[4][2];
            #pragma unroll
            for (int mi = 0; mi < 4; mi++) {
                int m = wm + mi * 16 + g;
                afr[mi][0] = __float_as_uint(As[(m    ) * QKV_AS_STRIDE + kk + q    ]);
                afr[mi][1] = __float_as_uint(As[(m + 8) * QKV_AS_STRIDE + kk + q    ]);
                afr[mi][2] = __float_as_uint(As[(m    ) * QKV_AS_STRIDE + kk + q + 4]);
                afr[mi][3] = __float_as_uint(As[(m + 8) * QKV_AS_STRIDE + kk + q + 4]);
            }
            #pragma unroll
            for (int ni = 0; ni < 4; ni++) {
                int n = wn + ni * 8 + g;
                bfr[ni][0] = __float_as_uint(Bs[(kk + q    ) * QKV_BS_STRIDE + n]);
                bfr[ni][1] = __float_as_uint(Bs[(kk + q + 4) * QKV_BS_STRIDE + n]);
            }
            #pragma unroll
            for (int mi = 0; mi < 4; mi++)
                #pragma unroll
                for (int ni = 0; ni < 4; ni++)
                    mma_tf32(acc[mi][ni], afr[mi][0], afr[mi][1], afr[mi][2], afr[mi][3],
                             bfr[ni][0], bfr[ni][1]);
        }
    };

    ldg_tile(0);
    sts_tile(0);
    __syncthreads();
    int buf = 0;
    for (int k0 = 32; k0 <= D_; k0 += 32) {
        bool has = (k0 < D_);
        if (has) ldg_tile(k0);
        compute(buf);
        if (has) sts_tile(buf ^ 1);
        __syncthreads();
        buf ^= 1;
    }

    #pragma unroll
    for (int mi = 0; mi < 4; mi++) {
        int m = mt * 128 + wm + mi * 16 + g;
        #pragma unroll
        for (int ni = 0; ni < 4; ni++) {
            int nn = wn + ni * 8 + q * 2;
            int hs = nn >> 6, d = nn & 63;
            int headslot = (n0 >> 6) + hs;
            float bz0 = bias[hc[hs] + d];
            float bz1 = bias[hc[hs] + d + 1];
            float* outp = Out + (((size_t)(b * A_ + headslot)) * S_) * DA_ + d;
            outp[(size_t)m * DA_ + 0]       = acc[mi][ni][0] + bz0;
            outp[(size_t)m * DA_ + 1]       = acc[mi][ni][1] + bz1;
            outp[(size_t)(m + 8) * DA_ + 0] = acc[mi][ni][2] + bz0;
            outp[(size_t)(m + 8) * DA_ + 1] = acc[mi][ni][3] + bz1;
        }
    }
}

// ---------------- kernel 4: flash attention on tf32 tensor cores (unchanged) ----------------
#define QS_STRIDE 68
#define KS_STRIDE 68
#define VS_STRIDE 72
#define QS_OFF    0
#define KS_OFF    (128 * QS_STRIDE)
#define VS_OFF    (KS_OFF + 128 * KS_STRIDE)
#define ATTN_TC_SMEM_FLOATS (VS_OFF + 128 * VS_STRIDE)

__global__ __launch_bounds__(256) void attn_tc_kernel() {
    extern __shared__ float sm[];
    float* Qs = sm + QS_OFF;
    float* Ks = sm + KS_OFF;
    float* Ps = sm + KS_OFF;
    float* Vs = sm + VS_OFF;

    int qt  = blockIdx.x;
    int bj  = blockIdx.y;
    int b   = bj >> 2, js = bj & 3;
    int tid = threadIdx.x;
    int wid  = tid >> 5;
    int lane = tid & 31;
    int g = lane >> 2, q = lane & 3;
    int wm = wid * 16;
    unsigned qmask = 0xffffffffu;

    const float* Qg = g_Q + (size_t)bj * S_ * DA_ + (size_t)qt * 128 * DA_;
    const float* Kg = g_K + (size_t)bj * S_ * DA_;
    const float* Vg = g_V + (size_t)bj * S_ * DA_;

    #pragma unroll
    for (int i = 0; i < 8; i++) {
        int f = tid + i * 256;
        int r = f >> 4, c = (f & 15) * 4;
        float4 v = ((const float4*)Qg)[f];
        Qs[r * QS_STRIDE + c + 0] = f2tf32(v.x);
        Qs[r * QS_STRIDE + c + 1] = f2tf32(v.y);
        Qs[r * QS_STRIDE + c + 2] = f2tf32(v.z);
        Qs[r * QS_STRIDE + c + 3] = f2tf32(v.w);
    }

    float Sfr[16][4];
    float Ofr[8][4];
    #pragma unroll
    for (int i = 0; i < 8; i++)
        #pragma unroll
        for (int c = 0; c < 4; c++) Ofr[i][c] = 0.f;
    float m0 = -1e30f, m1 = -1e30f, l0 = 0.f, l1 = 0.f;

    for (int t = 0; t < 16; t++) {
        __syncthreads();
        const float4* Kt = (const float4*)(Kg + (size_t)t * 128 * DA_);
        const float4* Vt = (const float4*)(Vg + (size_t)t * 128 * DA_);
        #pragma unroll
        for (int i = 0; i < 8; i++) {
            int f = tid + i * 256;
            int r = f >> 4, c = (f & 15) * 4;
            float4 kv = Kt[f];
            Ks[r * KS_STRIDE + c + 0] = f2tf32(kv.x);
            Ks[r * KS_STRIDE + c + 1] = f2tf32(kv.y);
            Ks[r * KS_STRIDE + c + 2] = f2tf32(kv.z);
            Ks[r * KS_STRIDE + c + 3] = f2tf32(kv.w);
            float4 vv = Vt[f];
            Vs[r * VS_STRIDE + c + 0] = f2tf32(vv.x);
            Vs[r * VS_STRIDE + c + 1] = f2tf32(vv.y);
            Vs[r * VS_STRIDE + c + 2] = f2tf32(vv.z);
            Vs[r * VS_STRIDE + c + 3] = f2tf32(vv.w);
        }
        __syncthreads();

        #pragma unroll
        for (int ni = 0; ni < 16; ni++)
            #pragma unroll
            for (int c = 0; c < 4; c++) Sfr[ni][c] = 0.f;

        #pragma unroll
        for (int ks = 0; ks < 8; ks++) {
            int kk = ks * 8;
            uint32_t a0 = __float_as_uint(Qs[(wm + g    ) * QS_STRIDE + kk + q    ]);
            uint32_t a1 = __float_as_uint(Qs[(wm + g + 8) * QS_STRIDE + kk + q    ]);
            uint32_t a2 = __float_as_uint(Qs[(wm + g    ) * QS_STRIDE + kk + q + 4]);
            uint32_t a3 = __float_as_uint(Qs[(wm + g + 8) * QS_STRIDE + kk + q + 4]);
            #pragma unroll
            for (int ni = 0; ni < 16; ni++) {
                int n = ni * 8 + g;
                uint32_t b0 = __float_as_uint(Ks[n * KS_STRIDE + kk + q    ]);
                uint32_t b1 = __float_as_uint(Ks[n * KS_STRIDE + kk + q + 4]);
                mma_tf32(Sfr[ni], a0, a1, a2, a3, b0, b1);
            }
        }

        float mx0 = -1e30f, mx1 = -1e30f;
        #pragma unroll
        for (int ni = 0; ni < 16; ni++) {
            mx0 = fmaxf(mx0, fmaxf(Sfr[ni][0], Sfr[ni][1]));
            mx1 = fmaxf(mx1, fmaxf(Sfr[ni][2], Sfr[ni][3]));
        }
        mx0 = fmaxf(mx0, __shfl_xor_sync(qmask, mx0, 1));
        mx0 = fmaxf(mx0, __shfl_xor_sync(qmask, mx0, 2));
        mx1 = fmaxf(mx1, __shfl_xor_sync(qmask, mx1, 1));
        mx1 = fmaxf(mx1, __shfl_xor_sync(qmask, mx1, 2));
        mx0 *= 0.125f; mx1 *= 0.125f;
        float mn0 = fmaxf(m0, mx0), mn1 = fmaxf(m1, mx1);
        float cr0 = __expf(m0 - mn0), cr1 = __expf(m1 - mn1);
        float ts0 = 0.f, ts1 = 0.f;
        #pragma unroll
        for (int ni = 0; ni < 16; ni++) {
            float p0 = __expf(Sfr[ni][0] * 0.125f - mn0);
            float p1 = __expf(Sfr[ni][1] * 0.125f - mn0);
            float p2 = __expf(Sfr[ni][2] * 0.125f - mn1);
            float p3 = __expf(Sfr[ni][3] * 0.125f - mn1);
            Sfr[ni][0] = p0; Sfr[ni][1] = p1; Sfr[ni][2] = p2; Sfr[ni][3] = p3;
            ts0 += p0 + p1; ts1 += p2 + p3;
        }
        ts0 += __shfl_xor_sync(qmask, ts0, 1);
        ts0 += __shfl_xor_sync(qmask, ts0, 2);
        ts1 += __shfl_xor_sync(qmask, ts1, 1);
        ts1 += __shfl_xor_sync(qmask, ts1, 2);
        l0 = l0 * cr0 + ts0;  m0 = mn0;
        l1 = l1 * cr1 + ts1;  m1 = mn1;
        #pragma unroll
        for (int i = 0; i < 8; i++) {
            Ofr[i][0] *= cr0; Ofr[i][1] *= cr0;
            Ofr[i][2] *= cr1; Ofr[i][3] *= cr1;
        }

        __syncthreads();

        #pragma unroll
        for (int ph = 0; ph < 2; ph++) {
            #pragma unroll
            for (int ni = 0; ni < 8; ni++) {
                int nig = ph * 8 + ni;
                float2 p01; p01.x = f2tf32(Sfr[nig][0]); p01.y = f2tf32(Sfr[nig][1]);
                float2 p23; p23.x = f2tf32(Sfr[nig][2]); p23.y = f2tf32(Sfr[nig][3]);
                *(float2*)&Ps[(wm + g    ) * KS_STRIDE + ni * 8 + 2 * q] = p01;
                *(float2*)&Ps[(wm + g + 8) * KS_STRIDE + ni * 8 + 2 * q] = p23;
            }
            __syncwarp();
            #pragma unroll
            for (int ks = 0; ks < 8; ks++) {
                int kk = ks * 8;
                uint32_t a0 = __float_as_uint(Ps[(wm + g    ) * KS_STRIDE + kk + q    ]);
                uint32_t a1 = __float_as_uint(Ps[(wm + g + 8) * KS_STRIDE + kk + q    ]);
                uint32_t a2 = __float_as_uint(Ps[(wm + g    ) * KS_STRIDE + kk + q + 4]);
                uint32_t a3 = __float_as_uint(Ps[(wm + g + 8) * KS_STRIDE + kk + q + 4]);
                int vr = ph * 64 + kk;
                #pragma unroll
                for (int ni = 0; ni < 8; ni++) {
                    int n = ni * 8 + g;
                    uint32_t b0 = __float_as_uint(Vs[(vr + q    ) * VS_STRIDE + n]);
                    uint32_t b1 = __float_as_uint(Vs[(vr + q + 4) * VS_STRIDE + n]);
                    mma_tf32(Ofr[ni], a0, a1, a2, a3, b0, b1);
                }
            }
            __syncwarp();
        }
    }

    float dist = g_dist[b * A_ + js];
    float sc0 = dist / l0, sc1 = dist / l1;
    int r0 = qt * 128 + wm + g, r1 = r0 + 8;
    float* z0 = g_O + ((size_t)(b * S_ + r0)) * (A_ * DA_) + js * 64;
    float* z1 = g_O + ((size_t)(b * S_ + r1)) * (A_ * DA_) + js * 64;
    #pragma unroll
    for (int ni = 0; ni < 8; ni++) {
        int c = ni * 8 + 2 * q;
        float2 v0; v0.x = Ofr[ni][0] * sc0; v0.y = Ofr[ni][1] * sc0;
        float2 v1; v1.x = Ofr[ni][2] * sc1; v1.y = Ofr[ni][3] * sc1;
        *(float2*)&z0[c] = v0;
        *(float2*)&z1[c] = v1;
    }
}

// ---------------- kernel 5: Z = O_final @ Wo + bo (tf32, KB=32 k-tile) ----------------
// M=16384, N=1024, K=256 -> 8 chunks of 32. Same layout as qkv KB=32.
__global__ __launch_bounds__(256, 2) void out_gemm_tf32(
    const float* __restrict__ Wo, const float* __restrict__ bo,
    float* __restrict__ Z)
{
    extern __shared__ float osm[];

    int m0 = blockIdx.y * 128;
    int n0 = blockIdx.x * 128;

    int tid  = threadIdx.x;
    int wid  = tid >> 5;
    int lane = tid & 31;
    int g    = lane >> 2, q = lane & 3;
    int wm   = (wid >> 2) * 64;
    int wn   = (wid & 3) * 32;

    float acc[4][4][4];
    #pragma unroll
    for (int mi = 0; mi < 4; mi++)
        #pragma unroll
        for (int ni = 0; ni < 4; ni++)
            #pragma unroll
            for (int c = 0; c < 4; c++) acc[mi][ni][c] = 0.f;

    float4 ra[4], rb[4];

    auto ldg_tile = [&](int k0) {
        #pragma unroll
        for (int i = 0; i < 4; i++) {
            int f   = tid + i * 256;
            int row = f >> 3, kc = (f & 7) * 4;
            ra[i] = *(const float4*)(g_O + (size_t)(m0 + row) * (A_ * DA_) + k0 + kc);
        }
        #pragma unroll
        for (int i = 0; i < 4; i++) {
            int f  = tid + i * 256;
            int kk = f >> 5, nn = (f & 31) * 4;
            rb[i] = *(const float4*)(Wo + (size_t)(k0 + kk) * D_ + n0 + nn);
        }
    };
    auto sts_tile = [&](int buf) {
        float* As = osm + buf * QKV_AS_SIZE;
        float* Bs = osm + 2 * QKV_AS_SIZE + buf * QKV_BS_SIZE;
        #pragma unroll
        for (int i = 0; i < 4; i++) {
            int f   = tid + i * 256;
            int row = f >> 3, kc = (f & 7) * 4;
            float* p = As + row * QKV_AS_STRIDE + kc;
            p[0] = f2tf32(ra[i].x);
            p[1] = f2tf32(ra[i].y);
            p[2] = f2tf32(ra[i].z);
            p[3] = f2tf32(ra[i].w);
        }
        #pragma unroll
        for (int i = 0; i < 4; i++) {
            int f  = tid + i * 256;
            int kk = f >> 5, nn = (f & 31) * 4;
            float* p = Bs + kk * QKV_BS_STRIDE + nn;
            p[0] = f2tf32(rb[i].x);
            p[1] = f2tf32(rb[i].y);
            p[2] = f2tf32(rb[i].z);
            p[3] = f2tf32(rb[i].w);
        }
    };
    auto compute = [&](int buf) {
        float* As = osm + buf * QKV_AS_SIZE;
        float* Bs = osm + 2 * QKV_AS_SIZE + buf * QKV_BS_SIZE;
        #pragma unroll
        for (int kk = 0; kk < 32; kk += 8) {
            uint32_t afr[4][4], bfr[4][2];
            #pragma unroll
            for (int mi = 0; mi < 4; mi++) {
                int m = wm + mi * 16 + g;
                afr[mi][0] = __float_as_uint(As[(m    ) * QKV_AS_STRIDE + kk + q    ]);
                afr[mi][1] = __float_as_uint(As[(m + 8) * QKV_AS_STRIDE + kk + q    ]);
                afr[mi][2] = __float_as_uint(As[(m    ) * QKV_AS_STRIDE + kk + q + 4]);
                afr[mi][3] = __float_as_uint(As[(m + 8) * QKV_AS_STRIDE + kk + q + 4]);
            }
            #pragma unroll
            for (int ni = 0; ni < 4; ni++) {
                int n = wn + ni * 8 + g;
                bfr[ni][0] = __float_as_uint(Bs[(kk + q    ) * QKV_BS_STRIDE + n]);
                bfr[ni][1] = __float_as_uint(Bs[(kk + q + 4) * QKV_BS_STRIDE + n]);
            }
            #pragma unroll
            for (int mi = 0; mi < 4; mi++)
                #pragma unroll
                for (int ni = 0; ni < 4; ni++)
                    mma_tf32(acc[mi][ni], afr[mi][0], afr[mi][1], afr[mi][2], afr[mi][3],
                             bfr[ni][0], bfr[ni][1]);
        }
    };

    ldg_tile(0);
    sts_tile(0);
    __syncthreads();
    int buf = 0;
    for (int k0 = 32; k0 <= A_ * DA_; k0 += 32) {
        bool has = (k0 < A_ * DA_);
        if (has) ldg_tile(k0);
        compute(buf);
        if (has) sts_tile(buf ^ 1);
        __syncthreads();
        buf ^= 1;
    }

    #pragma unroll
    for (int mi = 0; mi < 4; mi++) {
        int m = m0 + wm + mi * 16 + g;
        #pragma unroll
        for (int ni = 0; ni < 4; ni++) {
            int n = n0 + wn + ni * 8 + q * 2;
            float b0v = bo[n], b1v = bo[n + 1];
            Z[(size_t)m * D_ + n]           = acc[mi][ni][0] + b0v;
            Z[(size_t)m * D_ + n + 1]       = acc[mi][ni][1] + b1v;
            Z[(size_t)(m + 8) * D_ + n]     = acc[mi][ni][2] + b0v;
            Z[(size_t)(m + 8) * D_ + n + 1] = acc[mi][ni][3] + b1v;
        }
    }
}

// ---------------- launch ----------------
extern "C" void kernel_launch(void* const* d_in, const int* in_sizes, int n_in,
                              void* d_out, int out_size) {
    const float* x     = (const float*)d_in[0];
    const float* Wq    = (const float*)d_in[1];
    const float* bq    = (const float*)d_in[2];
    const float* Wk    = (const float*)d_in[3];
    const float* bk    = (const float*)d_in[4];
    const float* Wv    = (const float*)d_in[5];
    const float* bv    = (const float*)d_in[6];
    const float* Wr    = (const float*)d_in[7];
    const float* br    = (const float*)d_in[8];
    const float* gamma = (const float*)d_in[9];
    const float* beta  = (const float*)d_in[10];
    const float* Wo    = (const float*)d_in[11];
    const float* bo    = (const float*)d_in[12];
    float* Z = (float*)d_out;

    cudaFuncSetAttribute(attn_tc_kernel, cudaFuncAttributeMaxDynamicSharedMemorySize,
                         ATTN_TC_SMEM_FLOATS * (int)sizeof(float));
    cudaFuncSetAttribute(qkv_gemm_tf32, cudaFuncAttributeMaxDynamicSharedMemorySize,
                         QKV_SMEM_FLOATS * (int)sizeof(float));
    cudaFuncSetAttribute(out_gemm_tf32, cudaFuncAttributeMaxDynamicSharedMemorySize,
                         QKV_SMEM_FLOATS * (int)sizeof(float));

    zero_xbar_kernel<<<B_, 1024>>>();
    mean_kernel<<<dim3(32, B_), 1024>>>(x);
    router_kernel<<<B_, 512>>>(Wr, br, gamma, beta);
    qkv_gemm_tf32<<<dim3(6, 16, B_), 256, QKV_SMEM_FLOATS * (int)sizeof(float)>>>(
        x, Wq, bq, Wk, bk, Wv, bv);
    attn_tc_kernel<<<dim3(16, 32), 256, ATTN_TC_SMEM_FLOATS * (int)sizeof(float)>>>();
    out_gemm_tf32<<<dim3(8, 128), 256, QKV_SMEM_FLOATS * (int)sizeof(float)>>>(Wo, bo, Z);
}